// round 1
// baseline (speedup 1.0000x reference)
#include <cuda_runtime.h>
#include <cuda_bf16.h>
#include <math.h>

// Problem constants (shapes fixed by the dataset)
#define MAX_N 50000
#define MAX_E 800000
#define DIM 128         // in_dim == out_dim == 128
#define YDIM 256        // [global_maps | combined] packed per node

#define EPB 512         // edges per block in segment-sum

// Scratch (zero-init .bss, no allocations)
__device__ float g_Y[MAX_N * YDIM];      // Y[n][0:128]=x@Wg^T, Y[n][128:256]=x@(Wg+Wl)^T
__device__ float g_sums[MAX_N * DIM];    // segment sums
__device__ int   g_cnt[MAX_N];           // segment counts
__device__ float g_WT[DIM * YDIM];       // packed transposed weights: WT[k][j]

// ---------------------------------------------------------------------------
// Prep: WT[k][j] = Wg[j][k] for j<128, (Wg+Wl)[j-128][k] for j>=128
// ---------------------------------------------------------------------------
__global__ void prep_kernel(const float* __restrict__ Wg, const float* __restrict__ Wl)
{
    int t = blockIdx.x * blockDim.x + threadIdx.x;
    if (t >= DIM * YDIM) return;
    int k = t >> 8;        // / 256
    int j = t & 255;
    float v;
    if (j < DIM) {
        v = Wg[j * DIM + k];
    } else {
        int jj = j - DIM;
        v = Wg[jj * DIM + k] + Wl[jj * DIM + k];
    }
    g_WT[t] = v;
}

// ---------------------------------------------------------------------------
// Zero sums + cnt
// ---------------------------------------------------------------------------
__global__ void zero_kernel(int N)
{
    int stride = gridDim.x * blockDim.x;
    int t = blockIdx.x * blockDim.x + threadIdx.x;
    float4* s4 = reinterpret_cast<float4*>(g_sums);
    int n4 = N * (DIM / 4);
    for (int i = t; i < n4; i += stride) s4[i] = make_float4(0.f, 0.f, 0.f, 0.f);
    for (int i = t; i < N; i += stride) g_cnt[i] = 0;
}

// ---------------------------------------------------------------------------
// GEMM: Y[N,256] = x[N,128] @ WT  (WT is [128][256], i.e. B already transposed)
// 128x128 block tile, full K=128 resident in smem, 8x8 microtile, 256 threads
// ---------------------------------------------------------------------------
__global__ __launch_bounds__(256) void gemm_kernel(const float* __restrict__ A, int Nrows)
{
    extern __shared__ float sm[];
    float* As = sm;                // [128][128] row-major (m,k)
    float* Bs = sm + 128 * 128;    // [128][128] (k, n_local)

    const int bm = blockIdx.x * 128;
    const int bn = blockIdx.y * 128;
    const int tid = threadIdx.x;

    // Load A tile (rows bm..bm+127 are contiguous since full K width)
    {
        const float4* Ag = reinterpret_cast<const float4*>(A);
        float4* As4 = reinterpret_cast<float4*>(As);
        #pragma unroll
        for (int i = 0; i < 16; i++) {
            int u = tid + i * 256;            // 0..4095 float4 slots
            int row = bm + (u >> 5);          // 32 float4 per row
            float4 v = make_float4(0.f, 0.f, 0.f, 0.f);
            if (row < Nrows) v = Ag[bm * 32 + u];
            As4[u] = v;
        }
        // Load B tile: WT rows k=0..127, cols bn..bn+127 (coalesced copy)
        float4* Bs4 = reinterpret_cast<float4*>(Bs);
        #pragma unroll
        for (int i = 0; i < 16; i++) {
            int u = tid + i * 256;
            int k = u >> 5;
            int n4 = u & 31;
            Bs4[u] = reinterpret_cast<const float4*>(g_WT + k * YDIM + bn)[n4];
        }
    }
    __syncthreads();

    const int tx = tid & 15, ty = tid >> 4;
    const int m0 = ty * 8, n0 = tx * 8;

    float acc[8][8];
    #pragma unroll
    for (int i = 0; i < 8; i++)
        #pragma unroll
        for (int j = 0; j < 8; j++) acc[i][j] = 0.f;

    #pragma unroll 4
    for (int k = 0; k < 128; k++) {
        float a[8], b[8];
        *reinterpret_cast<float4*>(&b[0]) = *reinterpret_cast<const float4*>(&Bs[k * 128 + n0]);
        *reinterpret_cast<float4*>(&b[4]) = *reinterpret_cast<const float4*>(&Bs[k * 128 + n0 + 4]);
        #pragma unroll
        for (int i = 0; i < 8; i++) a[i] = As[(m0 + i) * 128 + k];
        #pragma unroll
        for (int i = 0; i < 8; i++)
            #pragma unroll
            for (int j = 0; j < 8; j++) acc[i][j] = fmaf(a[i], b[j], acc[i][j]);
    }

    #pragma unroll
    for (int i = 0; i < 8; i++) {
        int row = bm + m0 + i;
        if (row < Nrows) {
            float4* dst = reinterpret_cast<float4*>(&g_Y[row * YDIM + bn + n0]);
            dst[0] = make_float4(acc[i][0], acc[i][1], acc[i][2], acc[i][3]);
            dst[1] = make_float4(acc[i][4], acc[i][5], acc[i][6], acc[i][7]);
        }
    }
}

// ---------------------------------------------------------------------------
// Segment sum over sorted seg_ids. Each block owns EPB consecutive edges,
// 128 threads = one float per dim. Register accumulation; plain stores for
// block-owned segments, atomics only at block-boundary segments.
// ---------------------------------------------------------------------------
__global__ __launch_bounds__(128) void segsum_kernel(const int* __restrict__ nidx,
                                                     const int* __restrict__ sids,
                                                     int E)
{
    const int tid = threadIdx.x;
    int e0 = blockIdx.x * EPB;
    if (e0 >= E) return;
    int e1 = min(e0 + EPB, E);

    int cur = sids[e0];
    const bool first_partial = (e0 > 0) && (sids[e0 - 1] == cur);
    bool is_first = true;

    float acc = 0.f;
    int count = 0;
    int e = e0;

    // flush 'cur' mid-stream (segment ended inside this block)
    auto flush_mid = [&](int newseg) {
        if (is_first && first_partial) {
            atomicAdd(&g_sums[cur * DIM + tid], acc);
            if (tid == 0) atomicAdd(&g_cnt[cur], count);
        } else {
            g_sums[cur * DIM + tid] = acc;
            if (tid == 0) g_cnt[cur] = count;
        }
        is_first = false;
        acc = 0.f; count = 0; cur = newseg;
    };

    for (; e + 4 <= e1; e += 4) {
        int s0 = sids[e], s1 = sids[e + 1], s2 = sids[e + 2], s3 = sids[e + 3];
        int i0 = nidx[e], i1 = nidx[e + 1], i2 = nidx[e + 2], i3 = nidx[e + 3];
        // 4 independent gathered loads (MLP=4) from the L2-resident C half of Y
        float v0 = __ldg(&g_Y[i0 * YDIM + DIM + tid]);
        float v1 = __ldg(&g_Y[i1 * YDIM + DIM + tid]);
        float v2 = __ldg(&g_Y[i2 * YDIM + DIM + tid]);
        float v3 = __ldg(&g_Y[i3 * YDIM + DIM + tid]);
        if (s0 != cur) flush_mid(s0);
        acc += v0; count++;
        if (s1 != cur) flush_mid(s1);
        acc += v1; count++;
        if (s2 != cur) flush_mid(s2);
        acc += v2; count++;
        if (s3 != cur) flush_mid(s3);
        acc += v3; count++;
    }
    for (; e < e1; e++) {
        int s = sids[e];
        int i = nidx[e];
        float v = __ldg(&g_Y[i * YDIM + DIM + tid]);
        if (s != cur) flush_mid(s);
        acc += v; count++;
    }

    // final flush: atomic iff segment crosses a block boundary
    bool last_partial = (e1 < E) && (sids[e1] == cur);
    if ((is_first && first_partial) || last_partial) {
        atomicAdd(&g_sums[cur * DIM + tid], acc);
        if (tid == 0) atomicAdd(&g_cnt[cur], count);
    } else {
        g_sums[cur * DIM + tid] = acc;
        if (tid == 0) g_cnt[cur] = count;
    }
}

// ---------------------------------------------------------------------------
// Epilogue: mean / fallback + global + bias, then ELU
// ---------------------------------------------------------------------------
__global__ void epilogue_kernel(const float* __restrict__ bias, float* __restrict__ out, int N)
{
    int t = blockIdx.x * blockDim.x + threadIdx.x;
    if (t >= N * DIM) return;
    int n = t >> 7;
    int d = t & 127;
    float g = g_Y[n * YDIM + d];
    int c = g_cnt[n];
    float agg = (c > 0) ? (g_sums[t] / (float)c) : g;
    float o = agg + g + bias[d];
    out[t] = (o > 0.f) ? o : expm1f(o);
}

// ---------------------------------------------------------------------------
extern "C" void kernel_launch(void* const* d_in, const int* in_sizes, int n_in,
                              void* d_out, int out_size)
{
    const float* x    = (const float*)d_in[0];
    const float* Wg   = (const float*)d_in[1];
    const float* Wl   = (const float*)d_in[2];
    const float* bias = (const float*)d_in[3];
    const int*   nidx = (const int*)d_in[4];
    const int*   sids = (const int*)d_in[5];
    float* out = (float*)d_out;

    const int N = in_sizes[0] / DIM;
    const int E = in_sizes[4];

    cudaFuncSetAttribute(gemm_kernel, cudaFuncAttributeMaxDynamicSharedMemorySize, 131072);

    prep_kernel<<<(DIM * YDIM + 255) / 256, 256>>>(Wg, Wl);
    zero_kernel<<<1024, 256>>>(N);

    dim3 ggrid((N + 127) / 128, 2);
    gemm_kernel<<<ggrid, 256, 131072>>>(x, N);

    segsum_kernel<<<(E + EPB - 1) / EPB, 128>>>(nidx, sids, E);

    epilogue_kernel<<<(N * DIM + 255) / 256, 256>>>(bias, out, N);
}

// round 2
// speedup vs baseline: 1.2482x; 1.2482x over previous
#include <cuda_runtime.h>
#include <cuda_bf16.h>
#include <math.h>

#define MAX_N 50000
#define MAX_E 800000
#define DIM 128
#define YDIM 256

// Scratch (.bss device globals, no allocation)
__device__ float g_Y[MAX_N * YDIM];          // [n][0:128]=x@Wg^T, [n][128:256]=x@(Wg+Wl)^T
__device__ float g_WT[DIM * YDIM];           // WT[k][j]
__device__ int   g_rowptr[MAX_N + 1];        // CSR offsets into sorted seg_ids

// ---------------------------------------------------------------------------
// packed f32x2 FMA (Blackwell): d = a*b + d elementwise on {lo,hi}
// ---------------------------------------------------------------------------
__device__ __forceinline__ void ffma2(unsigned long long& d,
                                      unsigned long long a,
                                      unsigned long long b)
{
    asm("fma.rn.f32x2 %0, %1, %2, %0;" : "+l"(d) : "l"(a), "l"(b));
}
__device__ __forceinline__ float f2sum(unsigned long long v)
{
    return __uint_as_float((unsigned)v) + __uint_as_float((unsigned)(v >> 32));
}

// ---------------------------------------------------------------------------
// Prep: WT[k][j] = Wg[j][k] (j<128) | (Wg+Wl)[j-128][k]
// ---------------------------------------------------------------------------
__global__ void prep_kernel(const float* __restrict__ Wg, const float* __restrict__ Wl)
{
    int t = blockIdx.x * blockDim.x + threadIdx.x;
    if (t >= DIM * YDIM) return;
    int k = t >> 8;
    int j = t & 255;
    float v;
    if (j < DIM) v = Wg[j * DIM + k];
    else { int jj = j - DIM; v = Wg[jj * DIM + k] + Wl[jj * DIM + k]; }
    g_WT[t] = v;
}

// ---------------------------------------------------------------------------
// rowptr[n] = lower_bound(sids, n); rowptr[N] = E  (sids sorted)
// ---------------------------------------------------------------------------
__global__ void rowptr_kernel(const int* __restrict__ sids, int E, int N)
{
    int n = blockIdx.x * blockDim.x + threadIdx.x;
    if (n > N) return;
    int lo = 0, hi = E;
    while (lo < hi) {
        int mid = (lo + hi) >> 1;
        if (__ldg(&sids[mid]) < n) lo = mid + 1; else hi = mid;
    }
    g_rowptr[n] = lo;
}

// ---------------------------------------------------------------------------
// GEMM: Y[N,256] = x[N,128] @ WT   (per-block tile 128m x 128n, full K=128)
// FFMA2 microkernel: 8x8 accs as f32x2 pairs over interleaved even/odd k.
// smem: As[m][k] 64KB row-major, Bs2[kk][j] 64KB of float2{k=2kk, k=2kk+1}.
// ---------------------------------------------------------------------------
__global__ __launch_bounds__(256) void gemm_kernel(const float* __restrict__ A, int Nrows)
{
    extern __shared__ float sm[];
    float* As = sm;                                   // 128*128 floats
    float2* Bs2 = reinterpret_cast<float2*>(sm + 128 * 128);  // 64*128 float2

    const int bm = blockIdx.x * 128;
    const int bn = blockIdx.y * 128;
    const int tid = threadIdx.x;

    // load A tile (coalesced float4; rows are full K so tile is contiguous)
    {
        const float4* Ag = reinterpret_cast<const float4*>(A);
        float4* As4 = reinterpret_cast<float4*>(As);
        #pragma unroll
        for (int i = 0; i < 16; i++) {
            int u = tid + i * 256;               // 4096 float4 slots
            int row = bm + (u >> 5);
            float4 v = make_float4(0.f, 0.f, 0.f, 0.f);
            if (row < Nrows) v = Ag[bm * 32 + u];
            As4[u] = v;
        }
        // load B k-pair-interleaved: Bs2[kk*128+j] = {WT[2kk][bn+j], WT[2kk+1][bn+j]}
        #pragma unroll
        for (int i = 0; i < 32; i++) {
            int u = tid + i * 256;               // 8192 float2 slots
            int kk = u >> 7;
            int j  = u & 127;
            float lo = g_WT[(2 * kk)     * YDIM + bn + j];
            float hi = g_WT[(2 * kk + 1) * YDIM + bn + j];
            Bs2[u] = make_float2(lo, hi);
        }
    }
    __syncthreads();

    const int tx = tid & 15, ty = tid >> 4;
    const int m0 = ty * 8, n0 = tx * 8;

    unsigned long long acc2[8][8];
    #pragma unroll
    for (int i = 0; i < 8; i++)
        #pragma unroll
        for (int j = 0; j < 8; j++) acc2[i][j] = 0ULL;

    const unsigned long long* Bs2u = reinterpret_cast<const unsigned long long*>(Bs2);

    #pragma unroll 2
    for (int kk = 0; kk < 64; kk++) {
        unsigned long long a2[8], b2[8];
        // b pairs: 8 consecutive u64 (compiler vectorizes to LDS.128)
        #pragma unroll
        for (int j = 0; j < 8; j++) b2[j] = Bs2u[kk * 128 + n0 + j];
        // a pairs: {a(2kk), a(2kk+1)} direct from row-major As (8B aligned)
        #pragma unroll
        for (int i = 0; i < 8; i++)
            a2[i] = *reinterpret_cast<const unsigned long long*>(&As[(m0 + i) * 128 + 2 * kk]);
        #pragma unroll
        for (int i = 0; i < 8; i++)
            #pragma unroll
            for (int j = 0; j < 8; j++) ffma2(acc2[i][j], a2[i], b2[j]);
    }

    #pragma unroll
    for (int i = 0; i < 8; i++) {
        int row = bm + m0 + i;
        if (row < Nrows) {
            float4* dst = reinterpret_cast<float4*>(&g_Y[row * YDIM + bn + n0]);
            dst[0] = make_float4(f2sum(acc2[i][0]), f2sum(acc2[i][1]),
                                 f2sum(acc2[i][2]), f2sum(acc2[i][3]));
            dst[1] = make_float4(f2sum(acc2[i][4]), f2sum(acc2[i][5]),
                                 f2sum(acc2[i][6]), f2sum(acc2[i][7]));
        }
    }
}

// ---------------------------------------------------------------------------
// Gather + mean + epilogue, one warp per node. No atomics, no zero pass.
// ---------------------------------------------------------------------------
__global__ __launch_bounds__(256) void gather_kernel(const int* __restrict__ nidx,
                                                     const float* __restrict__ bias,
                                                     float* __restrict__ out, int N)
{
    int warp = (blockIdx.x * blockDim.x + threadIdx.x) >> 5;
    int lane = threadIdx.x & 31;
    if (warp >= N) return;

    int s = g_rowptr[warp];
    int e = g_rowptr[warp + 1];
    int d = lane * 4;

    float4 acc = make_float4(0.f, 0.f, 0.f, 0.f);
    int j = s;
    for (; j + 4 <= e; j += 4) {
        int i0 = __ldg(&nidx[j]);
        int i1 = __ldg(&nidx[j + 1]);
        int i2 = __ldg(&nidx[j + 2]);
        int i3 = __ldg(&nidx[j + 3]);
        float4 v0 = *reinterpret_cast<const float4*>(&g_Y[i0 * YDIM + DIM + d]);
        float4 v1 = *reinterpret_cast<const float4*>(&g_Y[i1 * YDIM + DIM + d]);
        float4 v2 = *reinterpret_cast<const float4*>(&g_Y[i2 * YDIM + DIM + d]);
        float4 v3 = *reinterpret_cast<const float4*>(&g_Y[i3 * YDIM + DIM + d]);
        acc.x += v0.x + v1.x + v2.x + v3.x;
        acc.y += v0.y + v1.y + v2.y + v3.y;
        acc.z += v0.z + v1.z + v2.z + v3.z;
        acc.w += v0.w + v1.w + v2.w + v3.w;
    }
    for (; j < e; j++) {
        int i0 = __ldg(&nidx[j]);
        float4 v0 = *reinterpret_cast<const float4*>(&g_Y[i0 * YDIM + DIM + d]);
        acc.x += v0.x; acc.y += v0.y; acc.z += v0.z; acc.w += v0.w;
    }

    int cnt = e - s;
    float inv = (cnt > 0) ? (1.0f / (float)cnt) : 0.f;
    float4 g = *reinterpret_cast<const float4*>(&g_Y[warp * YDIM + d]);
    float4 b = *reinterpret_cast<const float4*>(&bias[d]);

    float4 o;
    o.x = ((cnt > 0) ? acc.x * inv : g.x) + g.x + b.x;
    o.y = ((cnt > 0) ? acc.y * inv : g.y) + g.y + b.y;
    o.z = ((cnt > 0) ? acc.z * inv : g.z) + g.z + b.z;
    o.w = ((cnt > 0) ? acc.w * inv : g.w) + g.w + b.w;
    o.x = (o.x > 0.f) ? o.x : expm1f(o.x);
    o.y = (o.y > 0.f) ? o.y : expm1f(o.y);
    o.z = (o.z > 0.f) ? o.z : expm1f(o.z);
    o.w = (o.w > 0.f) ? o.w : expm1f(o.w);

    *reinterpret_cast<float4*>(&out[warp * DIM + d]) = o;
}

// ---------------------------------------------------------------------------
extern "C" void kernel_launch(void* const* d_in, const int* in_sizes, int n_in,
                              void* d_out, int out_size)
{
    const float* x    = (const float*)d_in[0];
    const float* Wg   = (const float*)d_in[1];
    const float* Wl   = (const float*)d_in[2];
    const float* bias = (const float*)d_in[3];
    const int*   nidx = (const int*)d_in[4];
    const int*   sids = (const int*)d_in[5];
    float* out = (float*)d_out;

    const int N = in_sizes[0] / DIM;
    const int E = in_sizes[4];

    cudaFuncSetAttribute(gemm_kernel, cudaFuncAttributeMaxDynamicSharedMemorySize, 131072);

    prep_kernel<<<(DIM * YDIM + 255) / 256, 256>>>(Wg, Wl);
    rowptr_kernel<<<(N + 256) / 256, 256>>>(sids, E, N);

    dim3 ggrid((N + 127) / 128, 2);
    gemm_kernel<<<ggrid, 256, 131072>>>(x, N);

    int warps_needed = N;
    int blocks = (warps_needed * 32 + 255) / 256;
    gather_kernel<<<blocks, 256>>>(nidx, bias, out, N);
}

// round 3
// speedup vs baseline: 1.5612x; 1.2507x over previous
#include <cuda_runtime.h>
#include <cuda_bf16.h>
#include <math.h>

#define MAX_N 50000
#define MAX_E 800000
#define DIM 128
#define YDIM 256

#define AS_STRIDE 132   // padded row stride (floats) -> conflict-free A LDS.64

// Scratch (.bss device globals, no allocation)
__device__ float g_Y[MAX_N * YDIM];          // [n][0:128]=x@Wg^T, [n][128:256]=x@(Wg+Wl)^T
__device__ float g_WT[DIM * YDIM];           // WT[k][j]
__device__ int   g_rowptr[MAX_N + 1];        // CSR offsets into sorted seg_ids

// ---------------------------------------------------------------------------
// packed f32x2 FMA (Blackwell): d = a*b + d elementwise on {lo,hi}
// ---------------------------------------------------------------------------
__device__ __forceinline__ void ffma2(unsigned long long& d,
                                      unsigned long long a,
                                      unsigned long long b)
{
    asm("fma.rn.f32x2 %0, %1, %2, %0;" : "+l"(d) : "l"(a), "l"(b));
}
__device__ __forceinline__ float f2sum(unsigned long long v)
{
    return __uint_as_float((unsigned)v) + __uint_as_float((unsigned)(v >> 32));
}

// ---------------------------------------------------------------------------
// Prep: WT[k][j] = Wg[j][k] (j<128) | (Wg+Wl)[j-128][k]
// ---------------------------------------------------------------------------
__global__ void prep_kernel(const float* __restrict__ Wg, const float* __restrict__ Wl)
{
    int t = blockIdx.x * blockDim.x + threadIdx.x;
    if (t >= DIM * YDIM) return;
    int k = t >> 8;
    int j = t & 255;
    float v;
    if (j < DIM) v = Wg[j * DIM + k];
    else { int jj = j - DIM; v = Wg[jj * DIM + k] + Wl[jj * DIM + k]; }
    g_WT[t] = v;
}

// ---------------------------------------------------------------------------
// rowptr[n] = lower_bound(sids, n); rowptr[N] = E  (sids sorted)
// ---------------------------------------------------------------------------
__global__ void rowptr_kernel(const int* __restrict__ sids, int E, int N)
{
    int n = blockIdx.x * blockDim.x + threadIdx.x;
    if (n > N) return;
    int lo = 0, hi = E;
    while (lo < hi) {
        int mid = (lo + hi) >> 1;
        if (__ldg(&sids[mid]) < n) lo = mid + 1; else hi = mid;
    }
    g_rowptr[n] = lo;
}

// ---------------------------------------------------------------------------
// GEMM: Y[N,256] = x[N,128] @ WT. Block tile 128m x 128n, full K=128 in smem.
// FFMA2 (k-pair) microkernel with conflict-free lane mapping:
//   warps 4x2 (warp tile 32m x 64n), lm = lane&3, ln = lane>>2
//   m rows: lm + 4*i (As padded stride 132 -> A LDS.64 on 4 distinct banks)
//   n cols: ln*4+{0..3} and +32   (B LDS.128 <=2 phases, broadcast elsewhere)
// ---------------------------------------------------------------------------
__global__ __launch_bounds__(256) void gemm_kernel(const float* __restrict__ A, int Nrows)
{
    extern __shared__ float sm[];
    float* As = sm;                                        // 128 * 132 floats
    unsigned long long* Bs2u =
        reinterpret_cast<unsigned long long*>(sm + 128 * AS_STRIDE);  // 64*128 u64

    const int bm = blockIdx.x * 128;
    const int bn = blockIdx.y * 128;
    const int tid = threadIdx.x;

    // load A tile (coalesced float4 from global; padded rows in smem)
    {
        const float4* Ag = reinterpret_cast<const float4*>(A);
        #pragma unroll
        for (int i = 0; i < 16; i++) {
            int u = tid + i * 256;               // 4096 float4 slots
            int rl = u >> 5;                     // local row
            int k4 = u & 31;                     // float4 index within row
            int row = bm + rl;
            float4 v = make_float4(0.f, 0.f, 0.f, 0.f);
            if (row < Nrows) v = Ag[bm * 32 + u];
            *reinterpret_cast<float4*>(&As[rl * AS_STRIDE + k4 * 4]) = v;
        }
        // load B k-pair-interleaved: Bs2u[kk*128+j] = {WT[2kk][bn+j], WT[2kk+1][bn+j]}
        #pragma unroll
        for (int i = 0; i < 32; i++) {
            int u = tid + i * 256;               // 8192 u64 slots
            int kk = u >> 7;
            int j  = u & 127;
            float lo = g_WT[(2 * kk)     * YDIM + bn + j];
            float hi = g_WT[(2 * kk + 1) * YDIM + bn + j];
            unsigned long long p = ((unsigned long long)__float_as_uint(hi) << 32)
                                 |  (unsigned long long)__float_as_uint(lo);
            Bs2u[u] = p;
        }
    }
    __syncthreads();

    const int wid    = tid >> 5;
    const int lane   = tid & 31;
    const int warp_m = wid >> 1;          // 0..3
    const int warp_n = wid & 1;           // 0..1
    const int lm     = lane & 3;          // 0..3
    const int ln     = lane >> 2;         // 0..7

    const int mbase = warp_m * 32 + lm;   // rows mbase + 4*i
    const int nbase = warp_n * 64 + ln * 4;

    unsigned long long acc2[8][8];
    #pragma unroll
    for (int i = 0; i < 8; i++)
        #pragma unroll
        for (int j = 0; j < 8; j++) acc2[i][j] = 0ULL;

    #pragma unroll 2
    for (int kk = 0; kk < 64; kk++) {
        unsigned long long a2[8], b2[8];
        // B: 4 x LDS.128 (2 u64 each), lanes at 32B stride -> <=2 phases
        const ulonglong2* bp0 = reinterpret_cast<const ulonglong2*>(&Bs2u[kk * 128 + nbase]);
        const ulonglong2* bp1 = reinterpret_cast<const ulonglong2*>(&Bs2u[kk * 128 + nbase + 32]);
        ulonglong2 q0 = bp0[0], q1 = bp0[1], q2 = bp1[0], q3 = bp1[1];
        b2[0] = q0.x; b2[1] = q0.y; b2[2] = q1.x; b2[3] = q1.y;
        b2[4] = q2.x; b2[5] = q2.y; b2[6] = q3.x; b2[7] = q3.y;
        // A: 8 x LDS.64, 4 distinct lm addresses on 4 distinct banks
        #pragma unroll
        for (int i = 0; i < 8; i++)
            a2[i] = *reinterpret_cast<const unsigned long long*>(
                        &As[(mbase + 4 * i) * AS_STRIDE + 2 * kk]);
        #pragma unroll
        for (int i = 0; i < 8; i++)
            #pragma unroll
            for (int j = 0; j < 8; j++) ffma2(acc2[i][j], a2[i], b2[j]);
    }

    #pragma unroll
    for (int i = 0; i < 8; i++) {
        int row = bm + mbase + 4 * i;
        if (row < Nrows) {
            float4* dst0 = reinterpret_cast<float4*>(&g_Y[row * YDIM + bn + nbase]);
            float4* dst1 = reinterpret_cast<float4*>(&g_Y[row * YDIM + bn + nbase + 32]);
            *dst0 = make_float4(f2sum(acc2[i][0]), f2sum(acc2[i][1]),
                                f2sum(acc2[i][2]), f2sum(acc2[i][3]));
            *dst1 = make_float4(f2sum(acc2[i][4]), f2sum(acc2[i][5]),
                                f2sum(acc2[i][6]), f2sum(acc2[i][7]));
        }
    }
}

// ---------------------------------------------------------------------------
// Gather + mean + epilogue, one warp per node. No atomics, no zero pass.
// ---------------------------------------------------------------------------
__global__ __launch_bounds__(256) void gather_kernel(const int* __restrict__ nidx,
                                                     const float* __restrict__ bias,
                                                     float* __restrict__ out, int N)
{
    int warp = (blockIdx.x * blockDim.x + threadIdx.x) >> 5;
    int lane = threadIdx.x & 31;
    if (warp >= N) return;

    int s = g_rowptr[warp];
    int e = g_rowptr[warp + 1];
    int d = lane * 4;

    float4 acc = make_float4(0.f, 0.f, 0.f, 0.f);
    int j = s;
    for (; j + 4 <= e; j += 4) {
        int i0 = __ldg(&nidx[j]);
        int i1 = __ldg(&nidx[j + 1]);
        int i2 = __ldg(&nidx[j + 2]);
        int i3 = __ldg(&nidx[j + 3]);
        float4 v0 = *reinterpret_cast<const float4*>(&g_Y[i0 * YDIM + DIM + d]);
        float4 v1 = *reinterpret_cast<const float4*>(&g_Y[i1 * YDIM + DIM + d]);
        float4 v2 = *reinterpret_cast<const float4*>(&g_Y[i2 * YDIM + DIM + d]);
        float4 v3 = *reinterpret_cast<const float4*>(&g_Y[i3 * YDIM + DIM + d]);
        acc.x += v0.x + v1.x + v2.x + v3.x;
        acc.y += v0.y + v1.y + v2.y + v3.y;
        acc.z += v0.z + v1.z + v2.z + v3.z;
        acc.w += v0.w + v1.w + v2.w + v3.w;
    }
    for (; j < e; j++) {
        int i0 = __ldg(&nidx[j]);
        float4 v0 = *reinterpret_cast<const float4*>(&g_Y[i0 * YDIM + DIM + d]);
        acc.x += v0.x; acc.y += v0.y; acc.z += v0.z; acc.w += v0.w;
    }

    int cnt = e - s;
    float inv = (cnt > 0) ? (1.0f / (float)cnt) : 0.f;
    float4 g = *reinterpret_cast<const float4*>(&g_Y[warp * YDIM + d]);
    float4 b = *reinterpret_cast<const float4*>(&bias[d]);

    float4 o;
    o.x = ((cnt > 0) ? acc.x * inv : g.x) + g.x + b.x;
    o.y = ((cnt > 0) ? acc.y * inv : g.y) + g.y + b.y;
    o.z = ((cnt > 0) ? acc.z * inv : g.z) + g.z + b.z;
    o.w = ((cnt > 0) ? acc.w * inv : g.w) + g.w + b.w;
    o.x = (o.x > 0.f) ? o.x : expm1f(o.x);
    o.y = (o.y > 0.f) ? o.y : expm1f(o.y);
    o.z = (o.z > 0.f) ? o.z : expm1f(o.z);
    o.w = (o.w > 0.f) ? o.w : expm1f(o.w);

    *reinterpret_cast<float4*>(&out[warp * DIM + d]) = o;
}

// ---------------------------------------------------------------------------
extern "C" void kernel_launch(void* const* d_in, const int* in_sizes, int n_in,
                              void* d_out, int out_size)
{
    const float* x    = (const float*)d_in[0];
    const float* Wg   = (const float*)d_in[1];
    const float* Wl   = (const float*)d_in[2];
    const float* bias = (const float*)d_in[3];
    const int*   nidx = (const int*)d_in[4];
    const int*   sids = (const int*)d_in[5];
    float* out = (float*)d_out;

    const int N = in_sizes[0] / DIM;
    const int E = in_sizes[4];

    const int smem_bytes = (128 * AS_STRIDE) * 4 + 64 * 128 * 8;  // 67584 + 65536
    cudaFuncSetAttribute(gemm_kernel, cudaFuncAttributeMaxDynamicSharedMemorySize, smem_bytes);

    prep_kernel<<<(DIM * YDIM + 255) / 256, 256>>>(Wg, Wl);
    rowptr_kernel<<<(N + 256) / 256, 256>>>(sids, E, N);

    dim3 ggrid((N + 127) / 128, 2);
    gemm_kernel<<<ggrid, 256, smem_bytes>>>(x, N);

    int blocks = (N * 32 + 255) / 256;
    gather_kernel<<<blocks, 256>>>(nidx, bias, out, N);
}

// round 5
// speedup vs baseline: 2.4960x; 1.5988x over previous
#include <cuda_runtime.h>
#include <cuda_bf16.h>
#include <math.h>
#include <stdint.h>

#define MAX_N 50000
#define DIM 128
#define YDIM 256

#define RS 272          // padded row stride in BYTES for bf16 tiles (136 elems)

// ---------------------------------------------------------------------------
// Scratch (.bss device globals, no allocations)
// ---------------------------------------------------------------------------
__device__ float g_Y[MAX_N * YDIM];              // [n][0:128]=x@Wg^T, [n][128:256]=x@(Wg+Wl)^T
__device__ int   g_rowptr[MAX_N + 1];            // CSR offsets into sorted seg_ids
// bf16 weight image, padded rows: [hi: 256 rows x 272B | lo: 256 rows x 272B]
__device__ __align__(16) unsigned char g_B[2 * 256 * RS];

// ---------------------------------------------------------------------------
// PTX helpers
// ---------------------------------------------------------------------------
static __device__ __forceinline__ uint32_t smem_u32(const void* p) {
    uint32_t a;
    asm("{ .reg .u64 t; cvta.to.shared.u64 t, %1; cvt.u32.u64 %0, t; }" : "=r"(a) : "l"(p));
    return a;
}

#define LDSM_X4(R, ADDR)                                                     \
    asm volatile("ldmatrix.sync.aligned.m8n8.x4.shared.b16 {%0,%1,%2,%3}, [%4];" \
                 : "=r"((R)[0]), "=r"((R)[1]), "=r"((R)[2]), "=r"((R)[3])    \
                 : "r"(ADDR))

#define MMA_BF16(D, A, B0, B1)                                               \
    asm volatile("mma.sync.aligned.m16n8k16.row.col.f32.bf16.bf16.f32 "      \
                 "{%0,%1,%2,%3}, {%4,%5,%6,%7}, {%8,%9}, {%0,%1,%2,%3};"     \
                 : "+f"((D)[0]), "+f"((D)[1]), "+f"((D)[2]), "+f"((D)[3])    \
                 : "r"((A)[0]), "r"((A)[1]), "r"((A)[2]), "r"((A)[3]),       \
                   "r"(B0), "r"(B1))

// ---------------------------------------------------------------------------
// Prep: bf16 hi/lo weight image with padded rows.
// row j<128: Wg[j][k]; row j>=128: Wg[j-128][k] + Wl[j-128][k]
// ---------------------------------------------------------------------------
__global__ void prepB_kernel(const float* __restrict__ Wg, const float* __restrict__ Wl)
{
    int t = blockIdx.x * blockDim.x + threadIdx.x;   // 0 .. 32767
    if (t >= 256 * 128) return;
    int j = t >> 7;
    int k = t & 127;
    float v;
    if (j < 128) v = Wg[j * DIM + k];
    else         v = Wg[(j - 128) * DIM + k] + Wl[(j - 128) * DIM + k];
    __nv_bfloat16 hi = __float2bfloat16(v);
    __nv_bfloat16 lo = __float2bfloat16(v - __bfloat162float(hi));
    *reinterpret_cast<__nv_bfloat16*>(&g_B[j * RS + k * 2]) = hi;
    *reinterpret_cast<__nv_bfloat16*>(&g_B[256 * RS + j * RS + k * 2]) = lo;
}

// ---------------------------------------------------------------------------
// rowptr[n] = lower_bound(sids, n)  (sids sorted)
// ---------------------------------------------------------------------------
__global__ void rowptr_kernel(const int* __restrict__ sids, int E, int N)
{
    int n = blockIdx.x * blockDim.x + threadIdx.x;
    if (n > N) return;
    int lo = 0, hi = E;
    while (lo < hi) {
        int mid = (lo + hi) >> 1;
        if (__ldg(&sids[mid]) < n) lo = mid + 1; else hi = mid;
    }
    g_rowptr[n] = lo;
}

// ---------------------------------------------------------------------------
// HMMA GEMM: per CTA one 128m x 256n tile, K=128.
// D = Ahi*Bhi + Ahi*Blo + Alo*Bhi (fp32 accum), bf16 2-term split.
// SMEM: A_hi[128xRS]@0 (34816), A_lo@34816, B_hi(256 rows)@69632, B_lo@139264
// ---------------------------------------------------------------------------
#define SM_A_HI 0
#define SM_A_LO 34816
#define SM_B_HI 69632
#define SM_B_LO (69632 + 69632)
#define SM_TOTAL (69632 + 2 * 69632)     // 208896 B

__global__ __launch_bounds__(256, 1) void gemm_tc_kernel(const float* __restrict__ A, int Nrows)
{
    extern __shared__ unsigned char smem[];
    const uint32_t sb = smem_u32(smem);
    const int tid  = threadIdx.x;
    const int wid  = tid >> 5;
    const int lane = tid & 31;
    const int bm   = blockIdx.x * 128;

    // ---- copy weight image (139264 B = 8704 uint4, 34 iters x 256 thr) ----
    {
        const uint4* src = reinterpret_cast<const uint4*>(g_B);
        uint4* dst = reinterpret_cast<uint4*>(smem + SM_B_HI);
        #pragma unroll
        for (int i = 0; i < 34; i++) dst[tid + i * 256] = src[tid + i * 256];
    }

    // ---- convert A tile fp32 -> bf16 hi/lo into padded smem ----
    {
        #pragma unroll
        for (int i = 0; i < 32; i++) {
            int u = tid + i * 256;            // 8192 k-pair slots
            int r  = u >> 6;                  // row 0..127
            int p  = u & 63;                  // k pair
            int row = bm + r;
            float2 v = make_float2(0.f, 0.f);
            if (row < Nrows)
                v = *reinterpret_cast<const float2*>(&A[row * DIM + 2 * p]);
            __nv_bfloat16 h0 = __float2bfloat16(v.x);
            __nv_bfloat16 h1 = __float2bfloat16(v.y);
            __nv_bfloat16 l0 = __float2bfloat16(v.x - __bfloat162float(h0));
            __nv_bfloat16 l1 = __float2bfloat16(v.y - __bfloat162float(h1));
            uint32_t hp = (uint32_t)__bfloat16_as_ushort(h0)
                        | ((uint32_t)__bfloat16_as_ushort(h1) << 16);
            uint32_t lp = (uint32_t)__bfloat16_as_ushort(l0)
                        | ((uint32_t)__bfloat16_as_ushort(l1) << 16);
            *reinterpret_cast<uint32_t*>(&smem[SM_A_HI + r * RS + p * 4]) = hp;
            *reinterpret_cast<uint32_t*>(&smem[SM_A_LO + r * RS + p * 4]) = lp;
        }
    }
    __syncthreads();

    // ---- per-lane ldmatrix address parts ----
    // A: tiles (rows m0..15 x k0..7 | k8..15): lane -> row (lane&15), kcol (lane>>4)*8
    const uint32_t aPart = (uint32_t)((lane & 15) * RS + (lane >> 4) * 16);
    // B: lanes -> n row (lane&7)+((lane>>4)<<3), kcol ((lane>>3)&1)*8  (NO trans:
    // W[n][k] row-major IS B col-major; plain ldmatrix yields the mma B fragment)
    const uint32_t bPart = (uint32_t)(((lane & 7) + ((lane >> 4) << 3)) * RS
                                      + ((lane >> 3) & 1) * 16);

    const uint32_t aHi = sb + SM_A_HI + aPart;
    const uint32_t aLo = sb + SM_A_LO + aPart;
    // warp handles n cols [w*16, w*16+16) in both halves
    const uint32_t bHi0 = sb + SM_B_HI + (uint32_t)(wid * 16) * RS + bPart;
    const uint32_t bHi1 = bHi0 + 128u * RS;
    const uint32_t bLo0 = sb + SM_B_LO + (uint32_t)(wid * 16) * RS + bPart;
    const uint32_t bLo1 = bLo0 + 128u * RS;

    float acc[8][4][4];
    #pragma unroll
    for (int i = 0; i < 8; i++)
        #pragma unroll
        for (int j = 0; j < 4; j++)
            #pragma unroll
            for (int q = 0; q < 4; q++) acc[i][j][q] = 0.f;

    #pragma unroll
    for (int ks = 0; ks < 8; ks++) {
        const uint32_t ko = (uint32_t)(ks * 32);   // 16 k * 2B
        uint32_t bh0[4], bh1[4], bl0[4], bl1[4];
        LDSM_X4(bh0, bHi0 + ko);
        LDSM_X4(bh1, bHi1 + ko);
        LDSM_X4(bl0, bLo0 + ko);
        LDSM_X4(bl1, bLo1 + ko);
        #pragma unroll
        for (int mf = 0; mf < 8; mf++) {
            uint32_t ah[4], al[4];
            LDSM_X4(ah, aHi + (uint32_t)(mf * 16) * RS + ko);
            LDSM_X4(al, aLo + (uint32_t)(mf * 16) * RS + ko);
            // half 0, nfrag 0/1
            MMA_BF16(acc[mf][0], ah, bh0[0], bh0[1]);
            MMA_BF16(acc[mf][0], ah, bl0[0], bl0[1]);
            MMA_BF16(acc[mf][0], al, bh0[0], bh0[1]);
            MMA_BF16(acc[mf][1], ah, bh0[2], bh0[3]);
            MMA_BF16(acc[mf][1], ah, bl0[2], bl0[3]);
            MMA_BF16(acc[mf][1], al, bh0[2], bh0[3]);
            // half 1, nfrag 0/1
            MMA_BF16(acc[mf][2], ah, bh1[0], bh1[1]);
            MMA_BF16(acc[mf][2], ah, bl1[0], bl1[1]);
            MMA_BF16(acc[mf][2], al, bh1[0], bh1[1]);
            MMA_BF16(acc[mf][3], ah, bh1[2], bh1[3]);
            MMA_BF16(acc[mf][3], ah, bl1[2], bl1[3]);
            MMA_BF16(acc[mf][3], al, bh1[2], bh1[3]);
        }
    }

    // ---- store accumulators to g_Y ----
    const int g  = lane >> 2;
    const int tg = lane & 3;
    #pragma unroll
    for (int mf = 0; mf < 8; mf++) {
        #pragma unroll
        for (int nf = 0; nf < 4; nf++) {
            int col = (nf >> 1) * 128 + wid * 16 + (nf & 1) * 8 + tg * 2;
            int row0 = bm + mf * 16 + g;
            int row1 = row0 + 8;
            if (row0 < Nrows)
                *reinterpret_cast<float2*>(&g_Y[row0 * YDIM + col]) =
                    make_float2(acc[mf][nf][0], acc[mf][nf][1]);
            if (row1 < Nrows)
                *reinterpret_cast<float2*>(&g_Y[row1 * YDIM + col]) =
                    make_float2(acc[mf][nf][2], acc[mf][nf][3]);
        }
    }
}

// ---------------------------------------------------------------------------
// Gather + mean + epilogue, one warp per node (at LTS cap already)
// ---------------------------------------------------------------------------
__global__ __launch_bounds__(256) void gather_kernel(const int* __restrict__ nidx,
                                                     const float* __restrict__ bias,
                                                     float* __restrict__ out, int N)
{
    int warp = (blockIdx.x * blockDim.x + threadIdx.x) >> 5;
    int lane = threadIdx.x & 31;
    if (warp >= N) return;

    int s = g_rowptr[warp];
    int e = g_rowptr[warp + 1];
    int d = lane * 4;

    float4 acc = make_float4(0.f, 0.f, 0.f, 0.f);
    int j = s;
    for (; j + 4 <= e; j += 4) {
        int i0 = __ldg(&nidx[j]);
        int i1 = __ldg(&nidx[j + 1]);
        int i2 = __ldg(&nidx[j + 2]);
        int i3 = __ldg(&nidx[j + 3]);
        float4 v0 = *reinterpret_cast<const float4*>(&g_Y[i0 * YDIM + DIM + d]);
        float4 v1 = *reinterpret_cast<const float4*>(&g_Y[i1 * YDIM + DIM + d]);
        float4 v2 = *reinterpret_cast<const float4*>(&g_Y[i2 * YDIM + DIM + d]);
        float4 v3 = *reinterpret_cast<const float4*>(&g_Y[i3 * YDIM + DIM + d]);
        acc.x += v0.x + v1.x + v2.x + v3.x;
        acc.y += v0.y + v1.y + v2.y + v3.y;
        acc.z += v0.z + v1.z + v2.z + v3.z;
        acc.w += v0.w + v1.w + v2.w + v3.w;
    }
    for (; j < e; j++) {
        int i0 = __ldg(&nidx[j]);
        float4 v0 = *reinterpret_cast<const float4*>(&g_Y[i0 * YDIM + DIM + d]);
        acc.x += v0.x; acc.y += v0.y; acc.z += v0.z; acc.w += v0.w;
    }

    int cnt = e - s;
    float inv = (cnt > 0) ? (1.0f / (float)cnt) : 0.f;
    float4 g = *reinterpret_cast<const float4*>(&g_Y[warp * YDIM + d]);
    float4 b = *reinterpret_cast<const float4*>(&bias[d]);

    float4 o;
    o.x = ((cnt > 0) ? acc.x * inv : g.x) + g.x + b.x;
    o.y = ((cnt > 0) ? acc.y * inv : g.y) + g.y + b.y;
    o.z = ((cnt > 0) ? acc.z * inv : g.z) + g.z + b.z;
    o.w = ((cnt > 0) ? acc.w * inv : g.w) + g.w + b.w;
    o.x = (o.x > 0.f) ? o.x : expm1f(o.x);
    o.y = (o.y > 0.f) ? o.y : expm1f(o.y);
    o.z = (o.z > 0.f) ? o.z : expm1f(o.z);
    o.w = (o.w > 0.f) ? o.w : expm1f(o.w);

    *reinterpret_cast<float4*>(&out[warp * DIM + d]) = o;
}

// ---------------------------------------------------------------------------
extern "C" void kernel_launch(void* const* d_in, const int* in_sizes, int n_in,
                              void* d_out, int out_size)
{
    const float* x    = (const float*)d_in[0];
    const float* Wg   = (const float*)d_in[1];
    const float* Wl   = (const float*)d_in[2];
    const float* bias = (const float*)d_in[3];
    const int*   nidx = (const int*)d_in[4];
    const int*   sids = (const int*)d_in[5];
    float* out = (float*)d_out;

    const int N = in_sizes[0] / DIM;
    const int E = in_sizes[4];

    cudaFuncSetAttribute(gemm_tc_kernel, cudaFuncAttributeMaxDynamicSharedMemorySize, SM_TOTAL);

    prepB_kernel<<<(256 * 128 + 255) / 256, 256>>>(Wg, Wl);
    rowptr_kernel<<<(N + 256) / 256, 256>>>(sids, E, N);

    gemm_tc_kernel<<<(N + 127) / 128, 256, SM_TOTAL>>>(x, N);

    int blocks = (N * 32 + 255) / 256;
    gather_kernel<<<blocks, 256>>>(nidx, bias, out, N);
}

// round 6
// speedup vs baseline: 2.5989x; 1.0412x over previous
#include <cuda_runtime.h>
#include <cuda_bf16.h>
#include <cuda_fp16.h>
#include <math.h>
#include <stdint.h>

#define MAX_N 50000
#define DIM 128
#define RS 272          // padded row stride in BYTES for bf16 tiles (136 elems)

// ---------------------------------------------------------------------------
// Scratch (.bss device globals, no allocations)
// ---------------------------------------------------------------------------
__device__ float g_Y[MAX_N * DIM];               // global half: x @ Wg^T (fp32)
__device__ __align__(16) __half2 g_Yc[MAX_N * 64];  // combined half: x @ (Wg+Wl)^T (fp16)
__device__ int   g_rowptr[MAX_N + 1];            // CSR offsets into sorted seg_ids
// bf16 weight image, padded rows: [hi: 256 rows x 272B | lo: 256 rows x 272B]
__device__ __align__(16) unsigned char g_B[2 * 256 * RS];

// ---------------------------------------------------------------------------
// PTX helpers
// ---------------------------------------------------------------------------
static __device__ __forceinline__ uint32_t smem_u32(const void* p) {
    uint32_t a;
    asm("{ .reg .u64 t; cvta.to.shared.u64 t, %1; cvt.u32.u64 %0, t; }" : "=r"(a) : "l"(p));
    return a;
}

#define LDSM_X4(R, ADDR)                                                     \
    asm volatile("ldmatrix.sync.aligned.m8n8.x4.shared.b16 {%0,%1,%2,%3}, [%4];" \
                 : "=r"((R)[0]), "=r"((R)[1]), "=r"((R)[2]), "=r"((R)[3])    \
                 : "r"(ADDR))

#define MMA_BF16(D, A, B0, B1)                                               \
    asm volatile("mma.sync.aligned.m16n8k16.row.col.f32.bf16.bf16.f32 "      \
                 "{%0,%1,%2,%3}, {%4,%5,%6,%7}, {%8,%9}, {%0,%1,%2,%3};"     \
                 : "+f"((D)[0]), "+f"((D)[1]), "+f"((D)[2]), "+f"((D)[3])    \
                 : "r"((A)[0]), "r"((A)[1]), "r"((A)[2]), "r"((A)[3]),       \
                   "r"(B0), "r"(B1))

// ---------------------------------------------------------------------------
// Prep: bf16 hi/lo weight image with padded rows.
// row j<128: Wg[j][k]; row j>=128: Wg[j-128][k] + Wl[j-128][k]
// ---------------------------------------------------------------------------
__global__ void prepB_kernel(const float* __restrict__ Wg, const float* __restrict__ Wl)
{
    int t = blockIdx.x * blockDim.x + threadIdx.x;   // 0 .. 32767
    if (t >= 256 * 128) return;
    int j = t >> 7;
    int k = t & 127;
    float v;
    if (j < 128) v = Wg[j * DIM + k];
    else         v = Wg[(j - 128) * DIM + k] + Wl[(j - 128) * DIM + k];
    __nv_bfloat16 hi = __float2bfloat16(v);
    __nv_bfloat16 lo = __float2bfloat16(v - __bfloat162float(hi));
    *reinterpret_cast<__nv_bfloat16*>(&g_B[j * RS + k * 2]) = hi;
    *reinterpret_cast<__nv_bfloat16*>(&g_B[256 * RS + j * RS + k * 2]) = lo;
}

// ---------------------------------------------------------------------------
// rowptr[n] = lower_bound(sids, n)  (sids sorted)
// ---------------------------------------------------------------------------
__global__ void rowptr_kernel(const int* __restrict__ sids, int E, int N)
{
    int n = blockIdx.x * blockDim.x + threadIdx.x;
    if (n > N) return;
    int lo = 0, hi = E;
    while (lo < hi) {
        int mid = (lo + hi) >> 1;
        if (__ldg(&sids[mid]) < n) lo = mid + 1; else hi = mid;
    }
    g_rowptr[n] = lo;
}

// ---------------------------------------------------------------------------
// HMMA GEMM: per CTA one 128m x 256n tile, K=128.
// D = Ahi*Bhi + Ahi*Blo + Alo*Bhi (fp32 accum), bf16 2-term split.
// Output: n-half 0 -> g_Y (fp32), n-half 1 -> g_Yc (fp16).
// ---------------------------------------------------------------------------
#define SM_A_HI 0
#define SM_A_LO 34816
#define SM_B_HI 69632
#define SM_B_LO (69632 + 69632)
#define SM_TOTAL (69632 + 2 * 69632)     // 208896 B

__global__ __launch_bounds__(256, 1) void gemm_tc_kernel(const float* __restrict__ A, int Nrows)
{
    extern __shared__ unsigned char smem[];
    const uint32_t sb = smem_u32(smem);
    const int tid  = threadIdx.x;
    const int wid  = tid >> 5;
    const int lane = tid & 31;
    const int bm   = blockIdx.x * 128;

    // ---- copy weight image (139264 B = 8704 uint4) ----
    {
        const uint4* src = reinterpret_cast<const uint4*>(g_B);
        uint4* dst = reinterpret_cast<uint4*>(smem + SM_B_HI);
        #pragma unroll
        for (int i = 0; i < 34; i++) dst[tid + i * 256] = src[tid + i * 256];
    }

    // ---- convert A tile fp32 -> bf16 hi/lo into padded smem ----
    {
        #pragma unroll
        for (int i = 0; i < 32; i++) {
            int u = tid + i * 256;            // 8192 k-pair slots
            int r  = u >> 6;                  // row 0..127
            int p  = u & 63;                  // k pair
            int row = bm + r;
            float2 v = make_float2(0.f, 0.f);
            if (row < Nrows)
                v = *reinterpret_cast<const float2*>(&A[row * DIM + 2 * p]);
            __nv_bfloat16 h0 = __float2bfloat16(v.x);
            __nv_bfloat16 h1 = __float2bfloat16(v.y);
            __nv_bfloat16 l0 = __float2bfloat16(v.x - __bfloat162float(h0));
            __nv_bfloat16 l1 = __float2bfloat16(v.y - __bfloat162float(h1));
            uint32_t hp = (uint32_t)__bfloat16_as_ushort(h0)
                        | ((uint32_t)__bfloat16_as_ushort(h1) << 16);
            uint32_t lp = (uint32_t)__bfloat16_as_ushort(l0)
                        | ((uint32_t)__bfloat16_as_ushort(l1) << 16);
            *reinterpret_cast<uint32_t*>(&smem[SM_A_HI + r * RS + p * 4]) = hp;
            *reinterpret_cast<uint32_t*>(&smem[SM_A_LO + r * RS + p * 4]) = lp;
        }
    }
    __syncthreads();

    // ---- per-lane ldmatrix address parts ----
    const uint32_t aPart = (uint32_t)((lane & 15) * RS + (lane >> 4) * 16);
    const uint32_t bPart = (uint32_t)(((lane & 7) + ((lane >> 4) << 3)) * RS
                                      + ((lane >> 3) & 1) * 16);

    const uint32_t aHi = sb + SM_A_HI + aPart;
    const uint32_t aLo = sb + SM_A_LO + aPart;
    const uint32_t bHi0 = sb + SM_B_HI + (uint32_t)(wid * 16) * RS + bPart;
    const uint32_t bHi1 = bHi0 + 128u * RS;
    const uint32_t bLo0 = sb + SM_B_LO + (uint32_t)(wid * 16) * RS + bPart;
    const uint32_t bLo1 = bLo0 + 128u * RS;

    float acc[8][4][4];
    #pragma unroll
    for (int i = 0; i < 8; i++)
        #pragma unroll
        for (int j = 0; j < 4; j++)
            #pragma unroll
            for (int q = 0; q < 4; q++) acc[i][j][q] = 0.f;

    #pragma unroll
    for (int ks = 0; ks < 8; ks++) {
        const uint32_t ko = (uint32_t)(ks * 32);   // 16 k * 2B
        uint32_t bh0[4], bh1[4], bl0[4], bl1[4];
        LDSM_X4(bh0, bHi0 + ko);
        LDSM_X4(bh1, bHi1 + ko);
        LDSM_X4(bl0, bLo0 + ko);
        LDSM_X4(bl1, bLo1 + ko);
        #pragma unroll
        for (int mf = 0; mf < 8; mf++) {
            uint32_t ah[4], al[4];
            LDSM_X4(ah, aHi + (uint32_t)(mf * 16) * RS + ko);
            LDSM_X4(al, aLo + (uint32_t)(mf * 16) * RS + ko);
            MMA_BF16(acc[mf][0], ah, bh0[0], bh0[1]);
            MMA_BF16(acc[mf][0], ah, bl0[0], bl0[1]);
            MMA_BF16(acc[mf][0], al, bh0[0], bh0[1]);
            MMA_BF16(acc[mf][1], ah, bh0[2], bh0[3]);
            MMA_BF16(acc[mf][1], ah, bl0[2], bl0[3]);
            MMA_BF16(acc[mf][1], al, bh0[2], bh0[3]);
            MMA_BF16(acc[mf][2], ah, bh1[0], bh1[1]);
            MMA_BF16(acc[mf][2], ah, bl1[0], bl1[1]);
            MMA_BF16(acc[mf][2], al, bh1[0], bh1[1]);
            MMA_BF16(acc[mf][3], ah, bh1[2], bh1[3]);
            MMA_BF16(acc[mf][3], ah, bl1[2], bl1[3]);
            MMA_BF16(acc[mf][3], al, bh1[2], bh1[3]);
        }
    }

    // ---- store: n-half 0 -> g_Y fp32, n-half 1 -> g_Yc fp16 ----
    const int g  = lane >> 2;
    const int tg = lane & 3;
    #pragma unroll
    for (int mf = 0; mf < 8; mf++) {
        int row0 = bm + mf * 16 + g;
        int row1 = row0 + 8;
        #pragma unroll
        for (int nf = 0; nf < 4; nf++) {
            int coll = wid * 16 + (nf & 1) * 8 + tg * 2;   // 0..127, even
            if (nf < 2) {
                if (row0 < Nrows)
                    *reinterpret_cast<float2*>(&g_Y[row0 * DIM + coll]) =
                        make_float2(acc[mf][nf][0], acc[mf][nf][1]);
                if (row1 < Nrows)
                    *reinterpret_cast<float2*>(&g_Y[row1 * DIM + coll]) =
                        make_float2(acc[mf][nf][2], acc[mf][nf][3]);
            } else {
                if (row0 < Nrows)
                    g_Yc[row0 * 64 + (coll >> 1)] =
                        __floats2half2_rn(acc[mf][nf][0], acc[mf][nf][1]);
                if (row1 < Nrows)
                    g_Yc[row1 * 64 + (coll >> 1)] =
                        __floats2half2_rn(acc[mf][nf][2], acc[mf][nf][3]);
            }
        }
    }
}

// ---------------------------------------------------------------------------
// Gather (fp16 rows, half traffic) + mean + epilogue, one warp per node
// ---------------------------------------------------------------------------
__global__ __launch_bounds__(256) void gather_kernel(const int* __restrict__ nidx,
                                                     const float* __restrict__ bias,
                                                     float* __restrict__ out, int N)
{
    int warp = (blockIdx.x * blockDim.x + threadIdx.x) >> 5;
    int lane = threadIdx.x & 31;
    if (warp >= N) return;

    int s = g_rowptr[warp];
    int e = g_rowptr[warp + 1];
    int d = lane * 4;               // 4 dims per lane
    int dh = lane * 2;              // half2 index within 64-wide row

    float4 acc = make_float4(0.f, 0.f, 0.f, 0.f);
    int j = s;
    for (; j + 4 <= e; j += 4) {
        int i0 = __ldg(&nidx[j]);
        int i1 = __ldg(&nidx[j + 1]);
        int i2 = __ldg(&nidx[j + 2]);
        int i3 = __ldg(&nidx[j + 3]);
        uint2 u0 = *reinterpret_cast<const uint2*>(&g_Yc[i0 * 64 + dh]);
        uint2 u1 = *reinterpret_cast<const uint2*>(&g_Yc[i1 * 64 + dh]);
        uint2 u2 = *reinterpret_cast<const uint2*>(&g_Yc[i2 * 64 + dh]);
        uint2 u3 = *reinterpret_cast<const uint2*>(&g_Yc[i3 * 64 + dh]);
        float2 a0 = __half22float2(*reinterpret_cast<__half2*>(&u0.x));
        float2 b0 = __half22float2(*reinterpret_cast<__half2*>(&u0.y));
        float2 a1 = __half22float2(*reinterpret_cast<__half2*>(&u1.x));
        float2 b1 = __half22float2(*reinterpret_cast<__half2*>(&u1.y));
        float2 a2 = __half22float2(*reinterpret_cast<__half2*>(&u2.x));
        float2 b2 = __half22float2(*reinterpret_cast<__half2*>(&u2.y));
        float2 a3 = __half22float2(*reinterpret_cast<__half2*>(&u3.x));
        float2 b3 = __half22float2(*reinterpret_cast<__half2*>(&u3.y));
        acc.x += a0.x + a1.x + a2.x + a3.x;
        acc.y += a0.y + a1.y + a2.y + a3.y;
        acc.z += b0.x + b1.x + b2.x + b3.x;
        acc.w += b0.y + b1.y + b2.y + b3.y;
    }
    for (; j < e; j++) {
        int i0 = __ldg(&nidx[j]);
        uint2 u0 = *reinterpret_cast<const uint2*>(&g_Yc[i0 * 64 + dh]);
        float2 a0 = __half22float2(*reinterpret_cast<__half2*>(&u0.x));
        float2 b0 = __half22float2(*reinterpret_cast<__half2*>(&u0.y));
        acc.x += a0.x; acc.y += a0.y; acc.z += b0.x; acc.w += b0.y;
    }

    int cnt = e - s;
    float inv = (cnt > 0) ? (1.0f / (float)cnt) : 0.f;
    float4 g = *reinterpret_cast<const float4*>(&g_Y[warp * DIM + d]);
    float4 b = *reinterpret_cast<const float4*>(&bias[d]);

    float4 o;
    o.x = ((cnt > 0) ? acc.x * inv : g.x) + g.x + b.x;
    o.y = ((cnt > 0) ? acc.y * inv : g.y) + g.y + b.y;
    o.z = ((cnt > 0) ? acc.z * inv : g.z) + g.z + b.z;
    o.w = ((cnt > 0) ? acc.w * inv : g.w) + g.w + b.w;
    o.x = (o.x > 0.f) ? o.x : expm1f(o.x);
    o.y = (o.y > 0.f) ? o.y : expm1f(o.y);
    o.z = (o.z > 0.f) ? o.z : expm1f(o.z);
    o.w = (o.w > 0.f) ? o.w : expm1f(o.w);

    *reinterpret_cast<float4*>(&out[warp * DIM + d]) = o;
}

// ---------------------------------------------------------------------------
extern "C" void kernel_launch(void* const* d_in, const int* in_sizes, int n_in,
                              void* d_out, int out_size)
{
    const float* x    = (const float*)d_in[0];
    const float* Wg   = (const float*)d_in[1];
    const float* Wl   = (const float*)d_in[2];
    const float* bias = (const float*)d_in[3];
    const int*   nidx = (const int*)d_in[4];
    const int*   sids = (const int*)d_in[5];
    float* out = (float*)d_out;

    const int N = in_sizes[0] / DIM;
    const int E = in_sizes[4];

    cudaFuncSetAttribute(gemm_tc_kernel, cudaFuncAttributeMaxDynamicSharedMemorySize, SM_TOTAL);

    prepB_kernel<<<(256 * 128 + 255) / 256, 256>>>(Wg, Wl);
    rowptr_kernel<<<(N + 256) / 256, 256>>>(sids, E, N);

    gemm_tc_kernel<<<(N + 127) / 128, 256, SM_TOTAL>>>(x, N);

    int blocks = (N * 32 + 255) / 256;
    gather_kernel<<<blocks, 256>>>(nidx, bias, out, N);
}

// round 7
// speedup vs baseline: 2.8092x; 1.0809x over previous
#include <cuda_runtime.h>
#include <cuda_bf16.h>
#include <cuda_fp16.h>
#include <math.h>
#include <stdint.h>

#define MAX_N 50000
#define DIM 128
#define RS 272          // padded row stride in BYTES for 16-bit tiles (136 elems)

// ---------------------------------------------------------------------------
// Scratch (.bss device globals, no allocations)
// ---------------------------------------------------------------------------
__device__ float g_Y[MAX_N * DIM];                  // global half: x @ Wg^T (fp32)
__device__ __align__(16) __half2 g_Yc[MAX_N * 64];  // combined half: x @ (Wg+Wl)^T (fp16)
__device__ int   g_rowptr[MAX_N + 1];               // CSR offsets into sorted seg_ids
// weight image: [Bg_hi bf16 | Bg_lo bf16 | Bc fp16], each 128 rows x RS bytes
__device__ __align__(16) unsigned char g_B[3 * 128 * RS];

// ---------------------------------------------------------------------------
// PTX helpers
// ---------------------------------------------------------------------------
static __device__ __forceinline__ uint32_t smem_u32(const void* p) {
    uint32_t a;
    asm("{ .reg .u64 t; cvta.to.shared.u64 t, %1; cvt.u32.u64 %0, t; }" : "=r"(a) : "l"(p));
    return a;
}

#define LDSM_X4(R, ADDR)                                                     \
    asm volatile("ldmatrix.sync.aligned.m8n8.x4.shared.b16 {%0,%1,%2,%3}, [%4];" \
                 : "=r"((R)[0]), "=r"((R)[1]), "=r"((R)[2]), "=r"((R)[3])    \
                 : "r"(ADDR))

#define MMA_BF16(D, A, B0, B1)                                               \
    asm volatile("mma.sync.aligned.m16n8k16.row.col.f32.bf16.bf16.f32 "      \
                 "{%0,%1,%2,%3}, {%4,%5,%6,%7}, {%8,%9}, {%0,%1,%2,%3};"     \
                 : "+f"((D)[0]), "+f"((D)[1]), "+f"((D)[2]), "+f"((D)[3])    \
                 : "r"((A)[0]), "r"((A)[1]), "r"((A)[2]), "r"((A)[3]),       \
                   "r"(B0), "r"(B1))

#define MMA_FP16(D, A, B0, B1)                                               \
    asm volatile("mma.sync.aligned.m16n8k16.row.col.f32.f16.f16.f32 "       \
                 "{%0,%1,%2,%3}, {%4,%5,%6,%7}, {%8,%9}, {%0,%1,%2,%3};"     \
                 : "+f"((D)[0]), "+f"((D)[1]), "+f"((D)[2]), "+f"((D)[3])    \
                 : "r"((A)[0]), "r"((A)[1]), "r"((A)[2]), "r"((A)[3]),       \
                   "r"(B0), "r"(B1))

// ---------------------------------------------------------------------------
// Prep: weight image. Bg = Wg (bf16 hi/lo), Bc = Wg+Wl (fp16 single)
// ---------------------------------------------------------------------------
__global__ void prepB_kernel(const float* __restrict__ Wg, const float* __restrict__ Wl)
{
    int t = blockIdx.x * blockDim.x + threadIdx.x;   // 0 .. 16383
    if (t >= 128 * 128) return;
    int j = t >> 7;
    int k = t & 127;
    float vg = Wg[j * DIM + k];
    float vc = vg + Wl[j * DIM + k];
    __nv_bfloat16 hi = __float2bfloat16(vg);
    __nv_bfloat16 lo = __float2bfloat16(vg - __bfloat162float(hi));
    *reinterpret_cast<__nv_bfloat16*>(&g_B[j * RS + k * 2]) = hi;
    *reinterpret_cast<__nv_bfloat16*>(&g_B[128 * RS + j * RS + k * 2]) = lo;
    *reinterpret_cast<__half*>(&g_B[2 * 128 * RS + j * RS + k * 2]) = __float2half_rn(vc);
}

// ---------------------------------------------------------------------------
// rowptr[n] = lower_bound(sids, n)  (sids sorted)
// ---------------------------------------------------------------------------
__global__ void rowptr_kernel(const int* __restrict__ sids, int E, int N)
{
    int n = blockIdx.x * blockDim.x + threadIdx.x;
    if (n > N) return;
    int lo = 0, hi = E;
    while (lo < hi) {
        int mid = (lo + hi) >> 1;
        if (__ldg(&sids[mid]) < n) lo = mid + 1; else hi = mid;
    }
    g_rowptr[n] = lo;
}

// ---------------------------------------------------------------------------
// HMMA GEMM: per CTA 128m rows, both 128n halves, K=128.
//   global half  (-> g_Y fp32):  3-pass bf16 split  (Ahi*Bhi + Ahi*Blo + Alo*Bhi)
//   combined half(-> g_Yc fp16): 1-pass fp16        (Af * Bc)
// ---------------------------------------------------------------------------
#define SM_A_HI  0
#define SM_A_LO  34816
#define SM_A_F16 69632
#define SM_BG_HI 104448
#define SM_BG_LO 139264
#define SM_BC    174080
#define SM_TOTAL 208896

__global__ __launch_bounds__(256, 1) void gemm_tc_kernel(const float* __restrict__ A, int Nrows)
{
    extern __shared__ unsigned char smem[];
    const uint32_t sb = smem_u32(smem);
    const int tid  = threadIdx.x;
    const int wid  = tid >> 5;
    const int lane = tid & 31;
    const int bm   = blockIdx.x * 128;

    // ---- copy weight image (104448 B = 6528 uint4) ----
    {
        const uint4* src = reinterpret_cast<const uint4*>(g_B);
        uint4* dst = reinterpret_cast<uint4*>(smem + SM_BG_HI);
        #pragma unroll
        for (int i = 0; i < 26; i++) {
            int u = tid + i * 256;
            if (u < 6528) dst[u] = src[u];
        }
    }

    // ---- convert A tile fp32 -> bf16 hi/lo + fp16 into padded smem ----
    {
        #pragma unroll
        for (int i = 0; i < 32; i++) {
            int u = tid + i * 256;            // 8192 k-pair slots
            int r  = u >> 6;                  // row 0..127
            int p  = u & 63;                  // k pair
            int row = bm + r;
            float2 v = make_float2(0.f, 0.f);
            if (row < Nrows)
                v = *reinterpret_cast<const float2*>(&A[row * DIM + 2 * p]);
            __nv_bfloat16 h0 = __float2bfloat16(v.x);
            __nv_bfloat16 h1 = __float2bfloat16(v.y);
            __nv_bfloat16 l0 = __float2bfloat16(v.x - __bfloat162float(h0));
            __nv_bfloat16 l1 = __float2bfloat16(v.y - __bfloat162float(h1));
            uint32_t hp = (uint32_t)__bfloat16_as_ushort(h0)
                        | ((uint32_t)__bfloat16_as_ushort(h1) << 16);
            uint32_t lp = (uint32_t)__bfloat16_as_ushort(l0)
                        | ((uint32_t)__bfloat16_as_ushort(l1) << 16);
            __half2 f2 = __floats2half2_rn(v.x, v.y);
            *reinterpret_cast<uint32_t*>(&smem[SM_A_HI  + r * RS + p * 4]) = hp;
            *reinterpret_cast<uint32_t*>(&smem[SM_A_LO  + r * RS + p * 4]) = lp;
            *reinterpret_cast<__half2*>(&smem[SM_A_F16 + r * RS + p * 4]) = f2;
        }
    }
    __syncthreads();

    // ---- per-lane ldmatrix address parts ----
    const uint32_t aPart = (uint32_t)((lane & 15) * RS + (lane >> 4) * 16);
    const uint32_t bPart = (uint32_t)(((lane & 7) + ((lane >> 4) << 3)) * RS
                                      + ((lane >> 3) & 1) * 16);

    const uint32_t aHi = sb + SM_A_HI  + aPart;
    const uint32_t aLo = sb + SM_A_LO  + aPart;
    const uint32_t aF  = sb + SM_A_F16 + aPart;
    const uint32_t bgH = sb + SM_BG_HI + (uint32_t)(wid * 16) * RS + bPart;
    const uint32_t bgL = sb + SM_BG_LO + (uint32_t)(wid * 16) * RS + bPart;
    const uint32_t bcF = sb + SM_BC    + (uint32_t)(wid * 16) * RS + bPart;

    float accG[8][2][4], accC[8][2][4];
    #pragma unroll
    for (int i = 0; i < 8; i++)
        #pragma unroll
        for (int j = 0; j < 2; j++)
            #pragma unroll
            for (int q = 0; q < 4; q++) { accG[i][j][q] = 0.f; accC[i][j][q] = 0.f; }

    #pragma unroll
    for (int ks = 0; ks < 8; ks++) {
        const uint32_t ko = (uint32_t)(ks * 32);   // 16 k * 2B
        uint32_t bh[4], bl[4], bf[4];
        LDSM_X4(bh, bgH + ko);
        LDSM_X4(bl, bgL + ko);
        LDSM_X4(bf, bcF + ko);
        #pragma unroll
        for (int mf = 0; mf < 8; mf++) {
            uint32_t ah[4], al[4], af[4];
            const uint32_t mo = (uint32_t)(mf * 16) * RS + ko;
            LDSM_X4(ah, aHi + mo);
            LDSM_X4(al, aLo + mo);
            LDSM_X4(af, aF  + mo);
            // global half: 3-pass bf16
            MMA_BF16(accG[mf][0], ah, bh[0], bh[1]);
            MMA_BF16(accG[mf][0], ah, bl[0], bl[1]);
            MMA_BF16(accG[mf][0], al, bh[0], bh[1]);
            MMA_BF16(accG[mf][1], ah, bh[2], bh[3]);
            MMA_BF16(accG[mf][1], ah, bl[2], bl[3]);
            MMA_BF16(accG[mf][1], al, bh[2], bh[3]);
            // combined half: 1-pass fp16
            MMA_FP16(accC[mf][0], af, bf[0], bf[1]);
            MMA_FP16(accC[mf][1], af, bf[2], bf[3]);
        }
    }

    // ---- store: global -> g_Y fp32, combined -> g_Yc fp16 ----
    const int g  = lane >> 2;
    const int tg = lane & 3;
    #pragma unroll
    for (int mf = 0; mf < 8; mf++) {
        int row0 = bm + mf * 16 + g;
        int row1 = row0 + 8;
        #pragma unroll
        for (int nf = 0; nf < 2; nf++) {
            int col = wid * 16 + nf * 8 + tg * 2;    // 0..127, even
            if (row0 < Nrows) {
                *reinterpret_cast<float2*>(&g_Y[row0 * DIM + col]) =
                    make_float2(accG[mf][nf][0], accG[mf][nf][1]);
                g_Yc[row0 * 64 + (col >> 1)] =
                    __floats2half2_rn(accC[mf][nf][0], accC[mf][nf][1]);
            }
            if (row1 < Nrows) {
                *reinterpret_cast<float2*>(&g_Y[row1 * DIM + col]) =
                    make_float2(accG[mf][nf][2], accG[mf][nf][3]);
                g_Yc[row1 * 64 + (col >> 1)] =
                    __floats2half2_rn(accC[mf][nf][2], accC[mf][nf][3]);
            }
        }
    }
}

// ---------------------------------------------------------------------------
// Gather: one warp per node; 16 lanes per edge row (LDG.128 each), two edges
// in flight across the half-warps; fp32 accumulation; shfl combine at end.
// ---------------------------------------------------------------------------
__global__ __launch_bounds__(256) void gather_kernel(const int* __restrict__ nidx,
                                                     const float* __restrict__ bias,
                                                     float* __restrict__ out, int N)
{
    int warp = (blockIdx.x * blockDim.x + threadIdx.x) >> 5;
    int lane = threadIdx.x & 31;
    if (warp >= N) return;

    const int half = lane >> 4;      // 0 | 1
    const int hl   = lane & 15;      // lane within half-warp

    int s = g_rowptr[warp];
    int e = g_rowptr[warp + 1];

    // lane covers 8 dims: hl*8 .. hl*8+7  (uint4 = 4 half2)
    float acc[8];
    #pragma unroll
    for (int q = 0; q < 8; q++) acc[q] = 0.f;

    int j = s;
    for (; j + 4 <= e; j += 4) {
        int i0 = __ldg(&nidx[j + half]);
        int i1 = __ldg(&nidx[j + 2 + half]);
        uint4 u0 = *reinterpret_cast<const uint4*>(&g_Yc[i0 * 64 + hl * 4]);
        uint4 u1 = *reinterpret_cast<const uint4*>(&g_Yc[i1 * 64 + hl * 4]);
        float2 p0 = __half22float2(*reinterpret_cast<__half2*>(&u0.x));
        float2 p1 = __half22float2(*reinterpret_cast<__half2*>(&u0.y));
        float2 p2 = __half22float2(*reinterpret_cast<__half2*>(&u0.z));
        float2 p3 = __half22float2(*reinterpret_cast<__half2*>(&u0.w));
        float2 q0 = __half22float2(*reinterpret_cast<__half2*>(&u1.x));
        float2 q1 = __half22float2(*reinterpret_cast<__half2*>(&u1.y));
        float2 q2 = __half22float2(*reinterpret_cast<__half2*>(&u1.z));
        float2 q3 = __half22float2(*reinterpret_cast<__half2*>(&u1.w));
        acc[0] += p0.x + q0.x; acc[1] += p0.y + q0.y;
        acc[2] += p1.x + q1.x; acc[3] += p1.y + q1.y;
        acc[4] += p2.x + q2.x; acc[5] += p2.y + q2.y;
        acc[6] += p3.x + q3.x; acc[7] += p3.y + q3.y;
    }
    if (j + 2 <= e) {
        int i0 = __ldg(&nidx[j + half]);
        uint4 u0 = *reinterpret_cast<const uint4*>(&g_Yc[i0 * 64 + hl * 4]);
        float2 p0 = __half22float2(*reinterpret_cast<__half2*>(&u0.x));
        float2 p1 = __half22float2(*reinterpret_cast<__half2*>(&u0.y));
        float2 p2 = __half22float2(*reinterpret_cast<__half2*>(&u0.z));
        float2 p3 = __half22float2(*reinterpret_cast<__half2*>(&u0.w));
        acc[0] += p0.x; acc[1] += p0.y; acc[2] += p1.x; acc[3] += p1.y;
        acc[4] += p2.x; acc[5] += p2.y; acc[6] += p3.x; acc[7] += p3.y;
        j += 2;
    }
    if (j < e && half == 0) {
        int i0 = __ldg(&nidx[j]);
        uint4 u0 = *reinterpret_cast<const uint4*>(&g_Yc[i0 * 64 + hl * 4]);
        float2 p0 = __half22float2(*reinterpret_cast<__half2*>(&u0.x));
        float2 p1 = __half22float2(*reinterpret_cast<__half2*>(&u0.y));
        float2 p2 = __half22float2(*reinterpret_cast<__half2*>(&u0.z));
        float2 p3 = __half22float2(*reinterpret_cast<__half2*>(&u0.w));
        acc[0] += p0.x; acc[1] += p0.y; acc[2] += p1.x; acc[3] += p1.y;
        acc[4] += p2.x; acc[5] += p2.y; acc[6] += p3.x; acc[7] += p3.y;
    }

    // combine the two half-warps (both end up with the full sums)
    #pragma unroll
    for (int q = 0; q < 8; q++)
        acc[q] += __shfl_xor_sync(0xffffffffu, acc[q], 16);

    // each half-warp writes its 4-dim quarter: dims hl*8 + half*4 .. +3
    int cnt = e - s;
    float inv = (cnt > 0) ? (1.0f / (float)cnt) : 0.f;
    int d = hl * 8 + half * 4;
    const float* ap = &acc[half * 4];

    float4 g = *reinterpret_cast<const float4*>(&g_Y[warp * DIM + d]);
    float4 b = *reinterpret_cast<const float4*>(&bias[d]);

    float4 o;
    o.x = ((cnt > 0) ? ap[0] * inv : g.x) + g.x + b.x;
    o.y = ((cnt > 0) ? ap[1] * inv : g.y) + g.y + b.y;
    o.z = ((cnt > 0) ? ap[2] * inv : g.z) + g.z + b.z;
    o.w = ((cnt > 0) ? ap[3] * inv : g.w) + g.w + b.w;
    o.x = (o.x > 0.f) ? o.x : expm1f(o.x);
    o.y = (o.y > 0.f) ? o.y : expm1f(o.y);
    o.z = (o.z > 0.f) ? o.z : expm1f(o.z);
    o.w = (o.w > 0.f) ? o.w : expm1f(o.w);

    *reinterpret_cast<float4*>(&out[warp * DIM + d]) = o;
}

// ---------------------------------------------------------------------------
extern "C" void kernel_launch(void* const* d_in, const int* in_sizes, int n_in,
                              void* d_out, int out_size)
{
    const float* x    = (const float*)d_in[0];
    const float* Wg   = (const float*)d_in[1];
    const float* Wl   = (const float*)d_in[2];
    const float* bias = (const float*)d_in[3];
    const int*   nidx = (const int*)d_in[4];
    const int*   sids = (const int*)d_in[5];
    float* out = (float*)d_out;

    const int N = in_sizes[0] / DIM;
    const int E = in_sizes[4];

    cudaFuncSetAttribute(gemm_tc_kernel, cudaFuncAttributeMaxDynamicSharedMemorySize, SM_TOTAL);

    prepB_kernel<<<(128 * 128 + 255) / 256, 256>>>(Wg, Wl);
    rowptr_kernel<<<(N + 256) / 256, 256>>>(sids, E, N);

    gemm_tc_kernel<<<(N + 127) / 128, 256, SM_TOTAL>>>(x, N);

    int blocks = (N * 32 + 255) / 256;
    gather_kernel<<<blocks, 256>>>(nidx, bias, out, N);
}

// round 8
// speedup vs baseline: 3.0922x; 1.1008x over previous
#include <cuda_runtime.h>
#include <cuda_bf16.h>
#include <cuda_fp16.h>
#include <math.h>
#include <stdint.h>

#define MAX_N 50000
#define DIM 128
#define RS 272          // padded row stride in BYTES for fp16 tiles (136 elems)

// ---------------------------------------------------------------------------
// Scratch (.bss device globals, no allocations)
// ---------------------------------------------------------------------------
__device__ float g_Y[MAX_N * DIM];                  // global half: x @ Wg^T (fp32)
__device__ __align__(16) __half2 g_Yc[MAX_N * 64];  // combined half: x @ (Wg+Wl)^T (fp16)
__device__ int   g_rowptr[MAX_N + 1];               // CSR offsets into sorted seg_ids
// weight image: [Bg_hi fp16 | Bg_lo fp16 | Bc fp16], each 128 rows x RS bytes
__device__ __align__(16) unsigned char g_B[3 * 128 * RS];

// ---------------------------------------------------------------------------
// PTX helpers
// ---------------------------------------------------------------------------
static __device__ __forceinline__ uint32_t smem_u32(const void* p) {
    uint32_t a;
    asm("{ .reg .u64 t; cvta.to.shared.u64 t, %1; cvt.u32.u64 %0, t; }" : "=r"(a) : "l"(p));
    return a;
}

#define LDSM_X4(R, ADDR)                                                     \
    asm volatile("ldmatrix.sync.aligned.m8n8.x4.shared.b16 {%0,%1,%2,%3}, [%4];" \
                 : "=r"((R)[0]), "=r"((R)[1]), "=r"((R)[2]), "=r"((R)[3])    \
                 : "r"(ADDR))

#define MMA_FP16(D, A, B0, B1)                                               \
    asm volatile("mma.sync.aligned.m16n8k16.row.col.f32.f16.f16.f32 "       \
                 "{%0,%1,%2,%3}, {%4,%5,%6,%7}, {%8,%9}, {%0,%1,%2,%3};"     \
                 : "+f"((D)[0]), "+f"((D)[1]), "+f"((D)[2]), "+f"((D)[3])    \
                 : "r"((A)[0]), "r"((A)[1]), "r"((A)[2]), "r"((A)[3]),       \
                   "r"(B0), "r"(B1))

// ---------------------------------------------------------------------------
// Prep: weight image. Bg = Wg as fp16 hi + fp16 residual lo; Bc = fp16(Wg+Wl)
// ---------------------------------------------------------------------------
__global__ void prepB_kernel(const float* __restrict__ Wg, const float* __restrict__ Wl)
{
    int t = blockIdx.x * blockDim.x + threadIdx.x;   // 0 .. 16383
    if (t >= 128 * 128) return;
    int j = t >> 7;
    int k = t & 127;
    float vg = Wg[j * DIM + k];
    float vc = vg + Wl[j * DIM + k];
    __half h = __float2half_rn(vg);
    __half l = __float2half_rn(vg - __half2float(h));
    *reinterpret_cast<__half*>(&g_B[j * RS + k * 2]) = h;
    *reinterpret_cast<__half*>(&g_B[128 * RS + j * RS + k * 2]) = l;
    *reinterpret_cast<__half*>(&g_B[2 * 128 * RS + j * RS + k * 2]) = __float2half_rn(vc);
}

// ---------------------------------------------------------------------------
// rowptr[n] = lower_bound(sids, n)  (sids sorted)
// ---------------------------------------------------------------------------
__global__ void rowptr_kernel(const int* __restrict__ sids, int E, int N)
{
    int n = blockIdx.x * blockDim.x + threadIdx.x;
    if (n > N) return;
    int lo = 0, hi = E;
    while (lo < hi) {
        int mid = (lo + hi) >> 1;
        if (__ldg(&sids[mid]) < n) lo = mid + 1; else hi = mid;
    }
    g_rowptr[n] = lo;
}

// ---------------------------------------------------------------------------
// HMMA GEMM: per CTA 128m rows, both 128n halves, K=128. fp16 A single copy.
//   global half  (-> g_Y fp32):  Af*Bg_hi + Af*Bg_lo  (B split exact)
//   combined half(-> g_Yc fp16): Af*Bc
// 384 HMMA / warp (was 512), A-convert trivial, smem 139264 B.
// ---------------------------------------------------------------------------
#define SM_A   0
#define SM_BH  34816
#define SM_BL  69632
#define SM_BC  104448
#define SM_TOTAL 139264

__global__ __launch_bounds__(256, 1) void gemm_tc_kernel(const float* __restrict__ A, int Nrows)
{
    extern __shared__ unsigned char smem[];
    const uint32_t sb = smem_u32(smem);
    const int tid  = threadIdx.x;
    const int wid  = tid >> 5;
    const int lane = tid & 31;
    const int bm   = blockIdx.x * 128;

    // ---- copy weight image (104448 B = 6528 uint4) ----
    {
        const uint4* src = reinterpret_cast<const uint4*>(g_B);
        uint4* dst = reinterpret_cast<uint4*>(smem + SM_BH);
        #pragma unroll
        for (int i = 0; i < 26; i++) {
            int u = tid + i * 256;
            if (u < 6528) dst[u] = src[u];
        }
    }

    // ---- convert A tile fp32 -> fp16 into padded smem (float4 -> 2x half2) ----
    {
        #pragma unroll
        for (int i = 0; i < 16; i++) {
            int u = tid + i * 256;            // 4096 float4 slots
            int r = u >> 5;                   // row 0..127
            int q = u & 31;                   // float4 within row
            int row = bm + r;
            float4 v = make_float4(0.f, 0.f, 0.f, 0.f);
            if (row < Nrows)
                v = *reinterpret_cast<const float4*>(&A[row * DIM + 4 * q]);
            __half2 h0 = __floats2half2_rn(v.x, v.y);
            __half2 h1 = __floats2half2_rn(v.z, v.w);
            *reinterpret_cast<__half2*>(&smem[SM_A + r * RS + q * 8])     = h0;
            *reinterpret_cast<__half2*>(&smem[SM_A + r * RS + q * 8 + 4]) = h1;
        }
    }
    __syncthreads();

    // ---- per-lane ldmatrix address parts ----
    const uint32_t aPart = (uint32_t)((lane & 15) * RS + (lane >> 4) * 16);
    const uint32_t bPart = (uint32_t)(((lane & 7) + ((lane >> 4) << 3)) * RS
                                      + ((lane >> 3) & 1) * 16);

    const uint32_t aF  = sb + SM_A  + aPart;
    const uint32_t bgH = sb + SM_BH + (uint32_t)(wid * 16) * RS + bPart;
    const uint32_t bgL = sb + SM_BL + (uint32_t)(wid * 16) * RS + bPart;
    const uint32_t bcF = sb + SM_BC + (uint32_t)(wid * 16) * RS + bPart;

    float accG[8][2][4], accC[8][2][4];
    #pragma unroll
    for (int i = 0; i < 8; i++)
        #pragma unroll
        for (int j = 0; j < 2; j++)
            #pragma unroll
            for (int q = 0; q < 4; q++) { accG[i][j][q] = 0.f; accC[i][j][q] = 0.f; }

    #pragma unroll
    for (int ks = 0; ks < 8; ks++) {
        const uint32_t ko = (uint32_t)(ks * 32);   // 16 k * 2B
        uint32_t bh[4], bl[4], bc[4];
        LDSM_X4(bh, bgH + ko);
        LDSM_X4(bl, bgL + ko);
        LDSM_X4(bc, bcF + ko);
        #pragma unroll
        for (int mf = 0; mf < 8; mf++) {
            uint32_t af[4];
            LDSM_X4(af, aF + (uint32_t)(mf * 16) * RS + ko);
            MMA_FP16(accG[mf][0], af, bh[0], bh[1]);
            MMA_FP16(accG[mf][0], af, bl[0], bl[1]);
            MMA_FP16(accG[mf][1], af, bh[2], bh[3]);
            MMA_FP16(accG[mf][1], af, bl[2], bl[3]);
            MMA_FP16(accC[mf][0], af, bc[0], bc[1]);
            MMA_FP16(accC[mf][1], af, bc[2], bc[3]);
        }
    }

    // ---- store: global -> g_Y fp32, combined -> g_Yc fp16 ----
    const int g  = lane >> 2;
    const int tg = lane & 3;
    #pragma unroll
    for (int mf = 0; mf < 8; mf++) {
        int row0 = bm + mf * 16 + g;
        int row1 = row0 + 8;
        #pragma unroll
        for (int nf = 0; nf < 2; nf++) {
            int col = wid * 16 + nf * 8 + tg * 2;    // 0..127, even
            if (row0 < Nrows) {
                *reinterpret_cast<float2*>(&g_Y[row0 * DIM + col]) =
                    make_float2(accG[mf][nf][0], accG[mf][nf][1]);
                g_Yc[row0 * 64 + (col >> 1)] =
                    __floats2half2_rn(accC[mf][nf][0], accC[mf][nf][1]);
            }
            if (row1 < Nrows) {
                *reinterpret_cast<float2*>(&g_Y[row1 * DIM + col]) =
                    make_float2(accG[mf][nf][2], accG[mf][nf][3]);
                g_Yc[row1 * 64 + (col >> 1)] =
                    __floats2half2_rn(accC[mf][nf][2], accC[mf][nf][3]);
            }
        }
    }
}

// ---------------------------------------------------------------------------
// Gather: one warp per node. Indices batched 32-at-a-time (one coalesced load),
// distributed via shfl (kills idx->data latency chain). Half-warp per edge.
// Blocks of 8 edges accumulate in fp16 (HADD2, 1 inst per half2 per edge),
// flushed to fp32; remainder uses exact fp32 path.
// ---------------------------------------------------------------------------
__global__ __launch_bounds__(256) void gather_kernel(const int* __restrict__ nidx,
                                                     const float* __restrict__ bias,
                                                     float* __restrict__ out, int N)
{
    int warp = (blockIdx.x * blockDim.x + threadIdx.x) >> 5;
    int lane = threadIdx.x & 31;
    if (warp >= N) return;

    const int half = lane >> 4;      // 0 | 1
    const int hl   = lane & 15;      // lane within half-warp

    int s = g_rowptr[warp];
    int e = g_rowptr[warp + 1];
    int cnt = e - s;

    float acc[8];
    #pragma unroll
    for (int q = 0; q < 8; q++) acc[q] = 0.f;

    for (int b0 = s; b0 < e; b0 += 32) {
        int m = min(32, e - b0);
        int idxv = 0;
        if (b0 + lane < e) idxv = __ldg(&nidx[b0 + lane]);

        int j = 0;
        // blocks of 8 edges (4 per half-warp), fp16 chunk accumulation
        for (; j + 8 <= m; j += 8) {
            __half2 c0 = __float2half2_rn(0.f), c1 = c0, c2 = c0, c3 = c0;
            #pragma unroll
            for (int t = 0; t < 4; t++) {
                int ii = __shfl_sync(0xffffffffu, idxv, j + 2 * t + half);
                uint4 u = *reinterpret_cast<const uint4*>(&g_Yc[ii * 64 + hl * 4]);
                c0 = __hadd2(c0, *reinterpret_cast<__half2*>(&u.x));
                c1 = __hadd2(c1, *reinterpret_cast<__half2*>(&u.y));
                c2 = __hadd2(c2, *reinterpret_cast<__half2*>(&u.z));
                c3 = __hadd2(c3, *reinterpret_cast<__half2*>(&u.w));
            }
            float2 f0 = __half22float2(c0);
            float2 f1 = __half22float2(c1);
            float2 f2 = __half22float2(c2);
            float2 f3 = __half22float2(c3);
            acc[0] += f0.x; acc[1] += f0.y; acc[2] += f1.x; acc[3] += f1.y;
            acc[4] += f2.x; acc[5] += f2.y; acc[6] += f3.x; acc[7] += f3.y;
        }
        // pairs (fp32 exact path)
        for (; j + 2 <= m; j += 2) {
            int ii = __shfl_sync(0xffffffffu, idxv, j + half);
            uint4 u = *reinterpret_cast<const uint4*>(&g_Yc[ii * 64 + hl * 4]);
            float2 p0 = __half22float2(*reinterpret_cast<__half2*>(&u.x));
            float2 p1 = __half22float2(*reinterpret_cast<__half2*>(&u.y));
            float2 p2 = __half22float2(*reinterpret_cast<__half2*>(&u.z));
            float2 p3 = __half22float2(*reinterpret_cast<__half2*>(&u.w));
            acc[0] += p0.x; acc[1] += p0.y; acc[2] += p1.x; acc[3] += p1.y;
            acc[4] += p2.x; acc[5] += p2.y; acc[6] += p3.x; acc[7] += p3.y;
        }
        // odd remainder (half 0 only)
        if (j < m) {
            int ii = __shfl_sync(0xffffffffu, idxv, j);
            if (half == 0) {
                uint4 u = *reinterpret_cast<const uint4*>(&g_Yc[ii * 64 + hl * 4]);
                float2 p0 = __half22float2(*reinterpret_cast<__half2*>(&u.x));
                float2 p1 = __half22float2(*reinterpret_cast<__half2*>(&u.y));
                float2 p2 = __half22float2(*reinterpret_cast<__half2*>(&u.z));
                float2 p3 = __half22float2(*reinterpret_cast<__half2*>(&u.w));
                acc[0] += p0.x; acc[1] += p0.y; acc[2] += p1.x; acc[3] += p1.y;
                acc[4] += p2.x; acc[5] += p2.y; acc[6] += p3.x; acc[7] += p3.y;
            }
        }
    }

    // combine the two half-warps
    #pragma unroll
    for (int q = 0; q < 8; q++)
        acc[q] += __shfl_xor_sync(0xffffffffu, acc[q], 16);

    float inv = (cnt > 0) ? (1.0f / (float)cnt) : 0.f;
    int d = hl * 8 + half * 4;
    const float* ap = &acc[half * 4];

    float4 g = *reinterpret_cast<const float4*>(&g_Y[warp * DIM + d]);
    float4 b = *reinterpret_cast<const float4*>(&bias[d]);

    float4 o;
    o.x = ((cnt > 0) ? ap[0] * inv : g.x) + g.x + b.x;
    o.y = ((cnt > 0) ? ap[1] * inv : g.y) + g.y + b.y;
    o.z = ((cnt > 0) ? ap[2] * inv : g.z) + g.z + b.z;
    o.w = ((cnt > 0) ? ap[3] * inv : g.w) + g.w + b.w;
    o.x = (o.x > 0.f) ? o.x : expm1f(o.x);
    o.y = (o.y > 0.f) ? o.y : expm1f(o.y);
    o.z = (o.z > 0.f) ? o.z : expm1f(o.z);
    o.w = (o.w > 0.f) ? o.w : expm1f(o.w);

    *reinterpret_cast<float4*>(&out[warp * DIM + d]) = o;
}

// ---------------------------------------------------------------------------
extern "C" void kernel_launch(void* const* d_in, const int* in_sizes, int n_in,
                              void* d_out, int out_size)
{
    const float* x    = (const float*)d_in[0];
    const float* Wg   = (const float*)d_in[1];
    const float* Wl   = (const float*)d_in[2];
    const float* bias = (const float*)d_in[3];
    const int*   nidx = (const int*)d_in[4];
    const int*   sids = (const int*)d_in[5];
    float* out = (float*)d_out;

    const int N = in_sizes[0] / DIM;
    const int E = in_sizes[4];

    cudaFuncSetAttribute(gemm_tc_kernel, cudaFuncAttributeMaxDynamicSharedMemorySize, SM_TOTAL);

    prepB_kernel<<<(128 * 128 + 255) / 256, 256>>>(Wg, Wl);
    rowptr_kernel<<<(N + 256) / 256, 256>>>(sids, E, N);

    gemm_tc_kernel<<<(N + 127) / 128, 256, SM_TOTAL>>>(x, N);

    int blocks = (N * 32 + 255) / 256;
    gather_kernel<<<blocks, 256>>>(nidx, bias, out, N);
}

// round 9
// speedup vs baseline: 3.2303x; 1.0446x over previous
#include <cuda_runtime.h>
#include <cuda_bf16.h>
#include <cuda_fp16.h>
#include <math.h>
#include <stdint.h>

#define MAX_N 50000
#define DIM 128
#define RS 272          // padded row stride in BYTES for fp16 tiles (136 elems)

// ---------------------------------------------------------------------------
// Scratch (.bss device globals, no allocations)
// ---------------------------------------------------------------------------
__device__ float g_Y[MAX_N * DIM];                  // global half: x @ Wg^T (fp32)
__device__ __align__(16) __half2 g_Yc[MAX_N * 64];  // combined half: x @ (Wg+Wl)^T (fp16)
__device__ int   g_rowptr[MAX_N + 1];               // CSR offsets into sorted seg_ids
// weight image: [Bg_hi fp16 | Bg_lo fp16 | Bc fp16], each 128 rows x RS bytes
__device__ __align__(16) unsigned char g_B[3 * 128 * RS];

// ---------------------------------------------------------------------------
// PTX helpers
// ---------------------------------------------------------------------------
static __device__ __forceinline__ uint32_t smem_u32(const void* p) {
    uint32_t a;
    asm("{ .reg .u64 t; cvta.to.shared.u64 t, %1; cvt.u32.u64 %0, t; }" : "=r"(a) : "l"(p));
    return a;
}

#define LDSM_X4(R, ADDR)                                                     \
    asm volatile("ldmatrix.sync.aligned.m8n8.x4.shared.b16 {%0,%1,%2,%3}, [%4];" \
                 : "=r"((R)[0]), "=r"((R)[1]), "=r"((R)[2]), "=r"((R)[3])    \
                 : "r"(ADDR))

#define MMA_FP16(D, A, B0, B1)                                               \
    asm volatile("mma.sync.aligned.m16n8k16.row.col.f32.f16.f16.f32 "       \
                 "{%0,%1,%2,%3}, {%4,%5,%6,%7}, {%8,%9}, {%0,%1,%2,%3};"     \
                 : "+f"((D)[0]), "+f"((D)[1]), "+f"((D)[2]), "+f"((D)[3])    \
                 : "r"((A)[0]), "r"((A)[1]), "r"((A)[2]), "r"((A)[3]),       \
                   "r"(B0), "r"(B1))

// ---------------------------------------------------------------------------
// Prep: weight image. Bg = Wg as fp16 hi + fp16 residual lo; Bc = fp16(Wg+Wl)
// ---------------------------------------------------------------------------
__global__ void prepB_kernel(const float* __restrict__ Wg, const float* __restrict__ Wl)
{
    int t = blockIdx.x * blockDim.x + threadIdx.x;   // 0 .. 16383
    if (t >= 128 * 128) return;
    int j = t >> 7;
    int k = t & 127;
    float vg = Wg[j * DIM + k];
    float vc = vg + Wl[j * DIM + k];
    __half h = __float2half_rn(vg);
    __half l = __float2half_rn(vg - __half2float(h));
    *reinterpret_cast<__half*>(&g_B[j * RS + k * 2]) = h;
    *reinterpret_cast<__half*>(&g_B[128 * RS + j * RS + k * 2]) = l;
    *reinterpret_cast<__half*>(&g_B[2 * 128 * RS + j * RS + k * 2]) = __float2half_rn(vc);
}

// ---------------------------------------------------------------------------
// rowptr[n] = lower_bound(sids, n)  (sids sorted)
// ---------------------------------------------------------------------------
__global__ void rowptr_kernel(const int* __restrict__ sids, int E, int N)
{
    int n = blockIdx.x * blockDim.x + threadIdx.x;
    if (n > N) return;
    int lo = 0, hi = E;
    while (lo < hi) {
        int mid = (lo + hi) >> 1;
        if (__ldg(&sids[mid]) < n) lo = mid + 1; else hi = mid;
    }
    g_rowptr[n] = lo;
}

// ---------------------------------------------------------------------------
// Persistent HMMA GEMM: grid = min(148, tiles). B image loaded ONCE per CTA,
// then loop over 128-row m-tiles with double-buffered A (1 sync per tile).
//   global half  (-> g_Y fp32):  Af*Bg_hi + Af*Bg_lo  (B split exact)
//   combined half(-> g_Yc fp16): Af*Bc
// ---------------------------------------------------------------------------
#define SM_A0  0
#define SM_A1  34816
#define SM_BH  69632
#define SM_BL  104448
#define SM_BC  139264
#define SM_TOTAL 174080

__global__ __launch_bounds__(256, 1) void gemm_tc_kernel(const float* __restrict__ A,
                                                         int Nrows, int ntiles)
{
    extern __shared__ unsigned char smem[];
    const uint32_t sb = smem_u32(smem);
    const int tid  = threadIdx.x;
    const int wid  = tid >> 5;
    const int lane = tid & 31;

    // ---- copy weight image ONCE (104448 B = 6528 uint4) ----
    {
        const uint4* src = reinterpret_cast<const uint4*>(g_B);
        uint4* dst = reinterpret_cast<uint4*>(smem + SM_BH);
        #pragma unroll
        for (int i = 0; i < 26; i++) {
            int u = tid + i * 256;
            if (u < 6528) dst[u] = src[u];
        }
    }
    // (B-read visibility is covered by the per-tile __syncthreads below)

    // ---- per-lane ldmatrix address parts ----
    const uint32_t aPart = (uint32_t)((lane & 15) * RS + (lane >> 4) * 16);
    const uint32_t bPart = (uint32_t)(((lane & 7) + ((lane >> 4) << 3)) * RS
                                      + ((lane >> 3) & 1) * 16);
    const uint32_t bgH = sb + SM_BH + (uint32_t)(wid * 16) * RS + bPart;
    const uint32_t bgL = sb + SM_BL + (uint32_t)(wid * 16) * RS + bPart;
    const uint32_t bcF = sb + SM_BC + (uint32_t)(wid * 16) * RS + bPart;

    const int g  = lane >> 2;
    const int tg = lane & 3;

    int buf = 0;
    for (int tile = blockIdx.x; tile < ntiles; tile += gridDim.x, buf ^= 1) {
        const int bm = tile * 128;
        const uint32_t aBase = buf ? SM_A1 : SM_A0;

        // ---- convert A tile fp32 -> fp16 into padded smem ----
        #pragma unroll
        for (int i = 0; i < 16; i++) {
            int u = tid + i * 256;            // 4096 float4 slots
            int r = u >> 5;                   // row 0..127
            int q = u & 31;                   // float4 within row
            int row = bm + r;
            float4 v = make_float4(0.f, 0.f, 0.f, 0.f);
            if (row < Nrows)
                v = *reinterpret_cast<const float4*>(&A[row * DIM + 4 * q]);
            __half2 h0 = __floats2half2_rn(v.x, v.y);
            __half2 h1 = __floats2half2_rn(v.z, v.w);
            *reinterpret_cast<__half2*>(&smem[aBase + r * RS + q * 8])     = h0;
            *reinterpret_cast<__half2*>(&smem[aBase + r * RS + q * 8 + 4]) = h1;
        }
        __syncthreads();   // convert(i) done everywhere => mainloop(i-1) drained too

        const uint32_t aF = sb + aBase + aPart;

        float accG[8][2][4], accC[8][2][4];
        #pragma unroll
        for (int i = 0; i < 8; i++)
            #pragma unroll
            for (int j = 0; j < 2; j++)
                #pragma unroll
                for (int q = 0; q < 4; q++) { accG[i][j][q] = 0.f; accC[i][j][q] = 0.f; }

        #pragma unroll
        for (int ks = 0; ks < 8; ks++) {
            const uint32_t ko = (uint32_t)(ks * 32);   // 16 k * 2B
            uint32_t bh[4], bl[4], bc[4];
            LDSM_X4(bh, bgH + ko);
            LDSM_X4(bl, bgL + ko);
            LDSM_X4(bc, bcF + ko);
            #pragma unroll
            for (int mf = 0; mf < 8; mf++) {
                uint32_t af[4];
                LDSM_X4(af, aF + (uint32_t)(mf * 16) * RS + ko);
                MMA_FP16(accG[mf][0], af, bh[0], bh[1]);
                MMA_FP16(accG[mf][0], af, bl[0], bl[1]);
                MMA_FP16(accG[mf][1], af, bh[2], bh[3]);
                MMA_FP16(accG[mf][1], af, bl[2], bl[3]);
                MMA_FP16(accC[mf][0], af, bc[0], bc[1]);
                MMA_FP16(accC[mf][1], af, bc[2], bc[3]);
            }
        }

        // ---- store: global -> g_Y fp32, combined -> g_Yc fp16 ----
        #pragma unroll
        for (int mf = 0; mf < 8; mf++) {
            int row0 = bm + mf * 16 + g;
            int row1 = row0 + 8;
            #pragma unroll
            for (int nf = 0; nf < 2; nf++) {
                int col = wid * 16 + nf * 8 + tg * 2;    // 0..127, even
                if (row0 < Nrows) {
                    *reinterpret_cast<float2*>(&g_Y[row0 * DIM + col]) =
                        make_float2(accG[mf][nf][0], accG[mf][nf][1]);
                    g_Yc[row0 * 64 + (col >> 1)] =
                        __floats2half2_rn(accC[mf][nf][0], accC[mf][nf][1]);
                }
                if (row1 < Nrows) {
                    *reinterpret_cast<float2*>(&g_Y[row1 * DIM + col]) =
                        make_float2(accG[mf][nf][2], accG[mf][nf][3]);
                    g_Yc[row1 * 64 + (col >> 1)] =
                        __floats2half2_rn(accC[mf][nf][2], accC[mf][nf][3]);
                }
            }
        }
    }
}

// ---------------------------------------------------------------------------
// Gather (R7 version): one warp per node; half-warp per edge (LDG.128/lane),
// fp32 accumulation, direct idx loads, shfl_xor(16) combine at end.
// ---------------------------------------------------------------------------
__global__ __launch_bounds__(256) void gather_kernel(const int* __restrict__ nidx,
                                                     const float* __restrict__ bias,
                                                     float* __restrict__ out, int N)
{
    int warp = (blockIdx.x * blockDim.x + threadIdx.x) >> 5;
    int lane = threadIdx.x & 31;
    if (warp >= N) return;

    const int half = lane >> 4;      // 0 | 1
    const int hl   = lane & 15;      // lane within half-warp

    int s = g_rowptr[warp];
    int e = g_rowptr[warp + 1];

    float acc[8];
    #pragma unroll
    for (int q = 0; q < 8; q++) acc[q] = 0.f;

    int j = s;
    for (; j + 4 <= e; j += 4) {
        int i0 = __ldg(&nidx[j + half]);
        int i1 = __ldg(&nidx[j + 2 + half]);
        uint4 u0 = *reinterpret_cast<const uint4*>(&g_Yc[i0 * 64 + hl * 4]);
        uint4 u1 = *reinterpret_cast<const uint4*>(&g_Yc[i1 * 64 + hl * 4]);
        float2 p0 = __half22float2(*reinterpret_cast<__half2*>(&u0.x));
        float2 p1 = __half22float2(*reinterpret_cast<__half2*>(&u0.y));
        float2 p2 = __half22float2(*reinterpret_cast<__half2*>(&u0.z));
        float2 p3 = __half22float2(*reinterpret_cast<__half2*>(&u0.w));
        float2 q0 = __half22float2(*reinterpret_cast<__half2*>(&u1.x));
        float2 q1 = __half22float2(*reinterpret_cast<__half2*>(&u1.y));
        float2 q2 = __half22float2(*reinterpret_cast<__half2*>(&u1.z));
        float2 q3 = __half22float2(*reinterpret_cast<__half2*>(&u1.w));
        acc[0] += p0.x + q0.x; acc[1] += p0.y + q0.y;
        acc[2] += p1.x + q1.x; acc[3] += p1.y + q1.y;
        acc[4] += p2.x + q2.x; acc[5] += p2.y + q2.y;
        acc[6] += p3.x + q3.x; acc[7] += p3.y + q3.y;
    }
    if (j + 2 <= e) {
        int i0 = __ldg(&nidx[j + half]);
        uint4 u0 = *reinterpret_cast<const uint4*>(&g_Yc[i0 * 64 + hl * 4]);
        float2 p0 = __half22float2(*reinterpret_cast<__half2*>(&u0.x));
        float2 p1 = __half22float2(*reinterpret_cast<__half2*>(&u0.y));
        float2 p2 = __half22float2(*reinterpret_cast<__half2*>(&u0.z));
        float2 p3 = __half22float2(*reinterpret_cast<__half2*>(&u0.w));
        acc[0] += p0.x; acc[1] += p0.y; acc[2] += p1.x; acc[3] += p1.y;
        acc[4] += p2.x; acc[5] += p2.y; acc[6] += p3.x; acc[7] += p3.y;
        j += 2;
    }
    if (j < e && half == 0) {
        int i0 = __ldg(&nidx[j]);
        uint4 u0 = *reinterpret_cast<const uint4*>(&g_Yc[i0 * 64 + hl * 4]);
        float2 p0 = __half22float2(*reinterpret_cast<__half2*>(&u0.x));
        float2 p1 = __half22float2(*reinterpret_cast<__half2*>(&u0.y));
        float2 p2 = __half22float2(*reinterpret_cast<__half2*>(&u0.z));
        float2 p3 = __half22float2(*reinterpret_cast<__half2*>(&u0.w));
        acc[0] += p0.x; acc[1] += p0.y; acc[2] += p1.x; acc[3] += p1.y;
        acc[4] += p2.x; acc[5] += p2.y; acc[6] += p3.x; acc[7] += p3.y;
    }

    // combine the two half-warps
    #pragma unroll
    for (int q = 0; q < 8; q++)
        acc[q] += __shfl_xor_sync(0xffffffffu, acc[q], 16);

    int cnt = e - s;
    float inv = (cnt > 0) ? (1.0f / (float)cnt) : 0.f;
    int d = hl * 8 + half * 4;
    const float* ap = &acc[half * 4];

    float4 g = *reinterpret_cast<const float4*>(&g_Y[warp * DIM + d]);
    float4 b = *reinterpret_cast<const float4*>(&bias[d]);

    float4 o;
    o.x = ((cnt > 0) ? ap[0] * inv : g.x) + g.x + b.x;
    o.y = ((cnt > 0) ? ap[1] * inv : g.y) + g.y + b.y;
    o.z = ((cnt > 0) ? ap[2] * inv : g.z) + g.z + b.z;
    o.w = ((cnt > 0) ? ap[3] * inv : g.w) + g.w + b.w;
    o.x = (o.x > 0.f) ? o.x : expm1f(o.x);
    o.y = (o.y > 0.f) ? o.y : expm1f(o.y);
    o.z = (o.z > 0.f) ? o.z : expm1f(o.z);
    o.w = (o.w > 0.f) ? o.w : expm1f(o.w);

    *reinterpret_cast<float4*>(&out[warp * DIM + d]) = o;
}

// ---------------------------------------------------------------------------
extern "C" void kernel_launch(void* const* d_in, const int* in_sizes, int n_in,
                              void* d_out, int out_size)
{
    const float* x    = (const float*)d_in[0];
    const float* Wg   = (const float*)d_in[1];
    const float* Wl   = (const float*)d_in[2];
    const float* bias = (const float*)d_in[3];
    const int*   nidx = (const int*)d_in[4];
    const int*   sids = (const int*)d_in[5];
    float* out = (float*)d_out;

    const int N = in_sizes[0] / DIM;
    const int E = in_sizes[4];

    cudaFuncSetAttribute(gemm_tc_kernel, cudaFuncAttributeMaxDynamicSharedMemorySize, SM_TOTAL);

    prepB_kernel<<<(128 * 128 + 255) / 256, 256>>>(Wg, Wl);
    rowptr_kernel<<<(N + 256) / 256, 256>>>(sids, E, N);

    const int ntiles = (N + 127) / 128;
    const int grid = ntiles < 148 ? ntiles : 148;
    gemm_tc_kernel<<<grid, 256, SM_TOTAL>>>(x, N, ntiles);

    int blocks = (N * 32 + 255) / 256;
    gather_kernel<<<blocks, 256>>>(nidx, bias, out, N);
}